// round 12
// baseline (speedup 1.0000x reference)
#include <cuda_runtime.h>
#include <cuda_fp16.h>
#include <cstdint>
#include <math.h>

#define HW   4096
#define NB   4
#define CIN  256
#define CK   64
#define CV   256
#define BQ   128
#define BK   64
#define NKT  (HW / BK)

#define PITCHE 72                 // tile row pitch (fp16 elements)
#define KT_BYTES  (64 * 144)      // 9216
#define VT_BYTES  (256 * 144)     // 36864

// ---------------- pre-tiled fp16 scratch ----------------
__device__ __align__(1024) __half g_kth[NB * 64 * 64 * PITCHE];   // K hi  [b][kt][r][d]
__device__ __align__(1024) __half g_ktl[NB * 64 * 64 * PITCHE];   // K lo
__device__ __align__(1024) __half g_vth[NB * 64 * 256 * PITCHE];  // V     [b][kt][c][j]
__device__ float g_C[NB * HW];                                    // diag logits |k_t|^2

// ---------------- helpers ----------------
__device__ __forceinline__ uint32_t smem_u32(const void* p) {
    uint32_t a;
    asm("{ .reg .u64 t; cvta.to.shared.u64 t, %1; cvt.u32.u64 %0, t; }" : "=r"(a) : "l"(p));
    return a;
}
__device__ __forceinline__ void bulkcp(uint32_t dst, const void* src, uint32_t bytes,
                                       uint32_t mbar) {
    asm volatile(
        "cp.async.bulk.shared::cluster.global.mbarrier::complete_tx::bytes [%0], [%1], %2, [%3];"
        :: "r"(dst), "l"(src), "r"(bytes), "r"(mbar) : "memory");
}
#define MBARRIER_INIT(mb, cnt) \
    asm volatile("mbarrier.init.shared.b64 [%0], %1;" :: "r"((uint32_t)(mb)), "r"((uint32_t)(cnt)) : "memory")
#define MBARRIER_EXPECT_TX(mb, tx) \
    asm volatile("mbarrier.arrive.expect_tx.shared.b64 _, [%0], %1;" :: "r"((uint32_t)(mb)), "r"((uint32_t)(tx)) : "memory")
#define MBARRIER_INVAL(mb) \
    asm volatile("mbarrier.inval.shared.b64 [%0];" :: "r"((uint32_t)(mb)) : "memory")
#define FENCE_ASYNC_SHARED() asm volatile("fence.proxy.async.shared::cta;" ::: "memory")
#define MBARRIER_WAIT_PARITY(mb, par) do { \
    uint32_t _mb = (uint32_t)(mb); uint32_t _p = (uint32_t)(par); uint32_t _done; \
    asm volatile("{\n\t.reg .pred p;\n\t" \
        "mbarrier.try_wait.parity.acquire.cta.shared::cta.b64 p, [%1], %2;\n\t" \
        "selp.b32 %0, 1, 0, p;\n\t}" : "=r"(_done) : "r"(_mb), "r"(_p) : "memory"); \
    if (!_done) { \
        asm volatile("{\n\t.reg .pred P1;\n\t" \
            "WL_%=:\n\t" \
            "mbarrier.try_wait.parity.acquire.cta.shared::cta.b64 P1, [%0], %1, 0x989680;\n\t" \
            "@P1 bra.uni WD_%=;\n\t" \
            "bra.uni WL_%=;\n\t" \
            "WD_%=:\n\t}" :: "r"(_mb), "r"(_p) : "memory"); \
    } } while (0)

__device__ __forceinline__ void ldsm4(uint32_t& r0, uint32_t& r1, uint32_t& r2, uint32_t& r3,
                                      uint32_t addr) {
    asm volatile("ldmatrix.sync.aligned.m8n8.x4.shared.b16 {%0,%1,%2,%3}, [%4];"
                 : "=r"(r0), "=r"(r1), "=r"(r2), "=r"(r3) : "r"(addr));
}
__device__ __forceinline__ void ldsm4t(uint32_t& r0, uint32_t& r1, uint32_t& r2, uint32_t& r3,
                                       uint32_t addr) {
    asm volatile("ldmatrix.sync.aligned.m8n8.x4.trans.shared.b16 {%0,%1,%2,%3}, [%4];"
                 : "=r"(r0), "=r"(r1), "=r"(r2), "=r"(r3) : "r"(addr));
}
__device__ __forceinline__ void mma16816(float (&d)[4],
                                         uint32_t a0, uint32_t a1, uint32_t a2, uint32_t a3,
                                         uint32_t b0, uint32_t b1) {
    asm volatile("mma.sync.aligned.m16n8k16.row.col.f32.f16.f16.f32 "
                 "{%0,%1,%2,%3}, {%4,%5,%6,%7}, {%8,%9}, {%0,%1,%2,%3};"
                 : "+f"(d[0]), "+f"(d[1]), "+f"(d[2]), "+f"(d[3])
                 : "r"(a0), "r"(a1), "r"(a2), "r"(a3), "r"(b0), "r"(b1));
}
__device__ __forceinline__ void hsplit(float x, __half& h, __half& l) {
    h = __float2half_rn(x);
    l = __float2half_rn(x - __half2float(h));
}
__device__ __forceinline__ uint32_t pack2h(__half a, __half b) {
    __half2 t(a, b);
    return *reinterpret_cast<uint32_t*>(&t);
}
__device__ __forceinline__ uint32_t packh2(float x, float y) {
    __half2 t = __floats2half2_rn(x, y);
    return *reinterpret_cast<uint32_t*>(&t);
}
__device__ __forceinline__ uint32_t packl2(float x, float y) {
    __half hx = __float2half_rn(x), hy = __float2half_rn(y);
    return pack2h(__float2half_rn(x - __half2float(hx)),
                  __float2half_rn(y - __half2float(hy)));
}

// ================= projection smem layouts =================
// x tile: [c(64)][t(128)] fp16, pitch 136 elts = 272B (trans-ldsm source)
#define PXH 0
#define PXL 17408
// W tile: [co][c(64)] fp16, pitch 72 elts = 144B
#define VWH 17408
#define PROJV_SMEM (17408 + 36864)          // 54272
#define KWH 34816
#define KWL 44032
#define KCP 53248
#define PROJK_SMEM (53248 + 512)            // 53760

// ---------------------------------------------------------------------------
// V projection: single-fp16 HMMA. Grid (32 t-tiles, NB). 256 thr.
// ---------------------------------------------------------------------------
__global__ __launch_bounds__(256) void proj_v(
    const float* __restrict__ x, const float* __restrict__ Wv,
    const float* __restrict__ bv)
{
    extern __shared__ char ps[];
    const uint32_t sb = smem_u32(ps);
    const int tid = threadIdx.x;
    const int w = tid >> 5, lane = tid & 31;
    const int g = lane >> 2, tig = lane & 3;
    const int wm = w & 3, wn = w >> 2;
    const int tx = blockIdx.x, b = blockIdx.y;
    const int t0 = tx * 128;

    const uint32_t a_row = lane & 15, a_col = (lane & 16) >> 1;
    const uint32_t bt_row = (lane & 7) + (lane & 8), bt_col = (lane & 16) >> 1;

    float d[4][8][4];
    #pragma unroll
    for (int mi = 0; mi < 4; mi++)
        #pragma unroll
        for (int nb = 0; nb < 8; nb++)
            #pragma unroll
            for (int r = 0; r < 4; r++) d[mi][nb][r] = 0.0f;

    for (int c0 = 0; c0 < CIN; c0 += 64) {
        __syncthreads();
        // x chunk [64 c][128 t] -> fp16
        #pragma unroll
        for (int it = 0; it < 8; it++) {
            int v = tid + it * 256;
            int c = v >> 5, t4 = v & 31;
            float4 f = *(const float4*)&x[((size_t)(b * CIN + c0 + c)) * HW + t0 + t4 * 4];
            uint2 u = make_uint2(packh2(f.x, f.y), packh2(f.z, f.w));
            *(uint2*)(ps + PXH + c * 272 + t4 * 8) = u;
        }
        // W chunk [256 co][64 c] -> fp16
        #pragma unroll
        for (int it = 0; it < 16; it++) {
            int v = tid + it * 256;
            int row = v >> 4, c4 = v & 15;
            float4 f = *(const float4*)&Wv[(size_t)row * CIN + c0 + c4 * 4];
            uint2 u = make_uint2(packh2(f.x, f.y), packh2(f.z, f.w));
            *(uint2*)(ps + VWH + row * 144 + c4 * 8) = u;
        }
        __syncthreads();

        #pragma unroll
        for (int ks = 0; ks < 4; ks++) {
            uint32_t a[4][4];
            #pragma unroll
            for (int mi = 0; mi < 4; mi++)
                ldsm4(a[mi][0], a[mi][1], a[mi][2], a[mi][3],
                      sb + VWH + (wm * 64 + mi * 16 + a_row) * 144 + (ks * 16 + a_col) * 2);
            #pragma unroll
            for (int nj = 0; nj < 4; nj++) {
                uint32_t b0, b1, b2, b3;
                ldsm4t(b0, b1, b2, b3,
                       sb + PXH + (ks * 16 + bt_row) * 272 + (wn * 64 + nj * 16 + bt_col) * 2);
                #pragma unroll
                for (int mi = 0; mi < 4; mi++) {
                    mma16816(d[mi][2 * nj],     a[mi][0], a[mi][1], a[mi][2], a[mi][3], b0, b1);
                    mma16816(d[mi][2 * nj + 1], a[mi][0], a[mi][1], a[mi][2], a[mi][3], b2, b3);
                }
            }
        }
    }

    // store: V tile [b][kt][c][j], kt = tx*2 + wn
    const int kt = tx * 2 + wn;
    __half* vt = g_vth + ((size_t)(b * 64 + kt) * 256) * PITCHE;
    #pragma unroll
    for (int mi = 0; mi < 4; mi++) {
        int coA = wm * 64 + mi * 16 + g;
        int coB = coA + 8;
        float bzA = bv[coA], bzB = bv[coB];
        #pragma unroll
        for (int nb = 0; nb < 8; nb++) {
            int j = nb * 8 + tig * 2;
            *(uint32_t*)&vt[(size_t)coA * PITCHE + j] =
                packh2(d[mi][nb][0] + bzA, d[mi][nb][1] + bzA);
            *(uint32_t*)&vt[(size_t)coB * PITCHE + j] =
                packh2(d[mi][nb][2] + bzB, d[mi][nb][3] + bzB);
        }
    }
}

// ---------------------------------------------------------------------------
// K projection: 3-term fp16-split HMMA + BN fold + diag C. Grid (32, NB).
// ---------------------------------------------------------------------------
__global__ __launch_bounds__(256) void proj_k(
    const float* __restrict__ x, const float* __restrict__ Wk,
    const float* __restrict__ bk,
    const float* __restrict__ bn_gamma, const float* __restrict__ bn_beta,
    const float* __restrict__ bn_mean,  const float* __restrict__ bn_var)
{
    extern __shared__ char ps[];
    const uint32_t sb = smem_u32(ps);
    const int tid = threadIdx.x;
    const int w = tid >> 5, lane = tid & 31;
    const int g = lane >> 2, tig = lane & 3;
    const int wm = w & 3, wn = w >> 2;
    const int tx = blockIdx.x, b = blockIdx.y;
    const int t0 = tx * 128;

    const uint32_t a_row = lane & 15, a_col = (lane & 16) >> 1;
    const uint32_t bt_row = (lane & 7) + (lane & 8), bt_col = (lane & 16) >> 1;

    float* CPf = (float*)(ps + KCP);
    if (tid < 128) CPf[tid] = 0.0f;

    float d[8][4];
    #pragma unroll
    for (int nb = 0; nb < 8; nb++)
        #pragma unroll
        for (int r = 0; r < 4; r++) d[nb][r] = 0.0f;

    for (int c0 = 0; c0 < CIN; c0 += 64) {
        __syncthreads();
        // x chunk hi/lo
        #pragma unroll
        for (int it = 0; it < 8; it++) {
            int v = tid + it * 256;
            int c = v >> 5, t4 = v & 31;
            float4 f = *(const float4*)&x[((size_t)(b * CIN + c0 + c)) * HW + t0 + t4 * 4];
            *(uint2*)(ps + PXH + c * 272 + t4 * 8) =
                make_uint2(packh2(f.x, f.y), packh2(f.z, f.w));
            *(uint2*)(ps + PXL + c * 272 + t4 * 8) =
                make_uint2(packl2(f.x, f.y), packl2(f.z, f.w));
        }
        // W chunk hi/lo (64 rows)
        #pragma unroll
        for (int it = 0; it < 4; it++) {
            int v = tid + it * 256;
            int row = v >> 4, c4 = v & 15;
            float4 f = *(const float4*)&Wk[(size_t)row * CIN + c0 + c4 * 4];
            *(uint2*)(ps + KWH + row * 144 + c4 * 8) =
                make_uint2(packh2(f.x, f.y), packh2(f.z, f.w));
            *(uint2*)(ps + KWL + row * 144 + c4 * 8) =
                make_uint2(packl2(f.x, f.y), packl2(f.z, f.w));
        }
        __syncthreads();

        #pragma unroll
        for (int ks = 0; ks < 4; ks++) {
            uint32_t ah[4], al[4];
            ldsm4(ah[0], ah[1], ah[2], ah[3],
                  sb + KWH + (wm * 16 + a_row) * 144 + (ks * 16 + a_col) * 2);
            ldsm4(al[0], al[1], al[2], al[3],
                  sb + KWL + (wm * 16 + a_row) * 144 + (ks * 16 + a_col) * 2);
            #pragma unroll
            for (int nj = 0; nj < 4; nj++) {
                uint32_t bh0, bh1, bh2, bh3, bl0, bl1, bl2, bl3;
                uint32_t xoff = (ks * 16 + bt_row) * 272 + (wn * 64 + nj * 16 + bt_col) * 2;
                ldsm4t(bh0, bh1, bh2, bh3, sb + PXH + xoff);
                ldsm4t(bl0, bl1, bl2, bl3, sb + PXL + xoff);
                mma16816(d[2 * nj],     ah[0], ah[1], ah[2], ah[3], bh0, bh1);
                mma16816(d[2 * nj],     ah[0], ah[1], ah[2], ah[3], bl0, bl1);
                mma16816(d[2 * nj],     al[0], al[1], al[2], al[3], bh0, bh1);
                mma16816(d[2 * nj + 1], ah[0], ah[1], ah[2], ah[3], bh2, bh3);
                mma16816(d[2 * nj + 1], ah[0], ah[1], ah[2], ah[3], bl2, bl3);
                mma16816(d[2 * nj + 1], al[0], al[1], al[2], al[3], bh2, bh3);
            }
        }
    }

    // BN fold, store K tile [b][kt][r][d] hi/lo, accumulate C = |k_t|^2
    const int co0 = wm * 16 + g, co1 = co0 + 8;
    float inv0 = bn_gamma[co0] * rsqrtf(bn_var[co0] + 1e-5f);
    float add0 = bn_beta[co0] - bn_mean[co0] * inv0 + bk[co0] * inv0;
    float inv1 = bn_gamma[co1] * rsqrtf(bn_var[co1] + 1e-5f);
    float add1 = bn_beta[co1] - bn_mean[co1] * inv1 + bk[co1] * inv1;
    const int kt = tx * 2 + wn;
    __half* kh = g_kth + ((size_t)(b * 64 + kt) * 64) * PITCHE;
    __half* kl = g_ktl + ((size_t)(b * 64 + kt) * 64) * PITCHE;

    #pragma unroll
    for (int nb = 0; nb < 8; nb++) {
        int r = nb * 8 + tig * 2;
        float k00 = d[nb][0] * inv0 + add0;   // (co0, r)
        float k01 = d[nb][1] * inv0 + add0;   // (co0, r+1)
        float k10 = d[nb][2] * inv1 + add1;   // (co1, r)
        float k11 = d[nb][3] * inv1 + add1;   // (co1, r+1)
        __half h, l;
        hsplit(k00, h, l); kh[(size_t)r * PITCHE + co0] = h;       kl[(size_t)r * PITCHE + co0] = l;
        hsplit(k01, h, l); kh[(size_t)(r + 1) * PITCHE + co0] = h; kl[(size_t)(r + 1) * PITCHE + co0] = l;
        hsplit(k10, h, l); kh[(size_t)r * PITCHE + co1] = h;       kl[(size_t)r * PITCHE + co1] = l;
        hsplit(k11, h, l); kh[(size_t)(r + 1) * PITCHE + co1] = h; kl[(size_t)(r + 1) * PITCHE + co1] = l;

        float s0 = k00 * k00 + k10 * k10;   // token r
        float s1 = k01 * k01 + k11 * k11;   // token r+1
        s0 += __shfl_xor_sync(0xffffffffu, s0, 4);
        s0 += __shfl_xor_sync(0xffffffffu, s0, 8);
        s0 += __shfl_xor_sync(0xffffffffu, s0, 16);
        s1 += __shfl_xor_sync(0xffffffffu, s1, 4);
        s1 += __shfl_xor_sync(0xffffffffu, s1, 8);
        s1 += __shfl_xor_sync(0xffffffffu, s1, 16);
        if (lane < 4) {
            atomicAdd(&CPf[wn * 64 + nb * 8 + lane * 2], s0);
            atomicAdd(&CPf[wn * 64 + nb * 8 + lane * 2 + 1], s1);
        }
    }
    __syncthreads();
    if (tid < 128) g_C[(size_t)b * HW + t0 + tid] = CPf[tid];
}

// ================= flash smem layout =================
#define PITCH  144
#define QH_OFF 0
#define QL_OFF 18432
#define KBASE  36864
#define KH(st) (KBASE + (st) * KT_BYTES)
#define KL(st) (KBASE + 2 * KT_BYTES + (st) * KT_BYTES)
#define VBASE  (KBASE + 4 * KT_BYTES)
#define VS(st) (VBASE + (st) * VT_BYTES)
#define MB_OFF (VBASE + 2 * VT_BYTES)
#define SMEM_TOTAL (MB_OFF + 64)
#define OS_OFF 0
#define OPITCH 132
#define STAGE_TX (2 * KT_BYTES + VT_BYTES)

// ---------------------------------------------------------------------------
// Flash: fixed-shift softmax (P = exp(s - C), no max, no rescale).
// ---------------------------------------------------------------------------
__global__ __launch_bounds__(256, 1) void flashm_kernel(float* __restrict__ out)
{
    extern __shared__ char smem[];
    const uint32_t sb = smem_u32(smem);
    const int tid  = threadIdx.x;
    const int w    = tid >> 5;
    const int lane = tid & 31;
    const int g    = lane >> 2;
    const int tig  = lane & 3;
    const int i0   = w * 16;

    const int qb = blockIdx.x;
    const int q0 = qb * BQ;
    const int b  = blockIdx.y;

    const char* kth = (const char*)g_kth + (size_t)(b * 64) * KT_BYTES;
    const char* ktl = (const char*)g_ktl + (size_t)(b * 64) * KT_BYTES;
    const char* vth = (const char*)g_vth + (size_t)(b * 64) * VT_BYTES;

    const uint32_t mb0 = sb + MB_OFF;
    const uint32_t mb1 = sb + MB_OFF + 8;

    if (tid == 0) {
        MBARRIER_INIT(mb0, 1);
        MBARRIER_INIT(mb1, 1);
        FENCE_ASYNC_SHARED();
    }
    __syncthreads();

    if (tid == 0) {
        MBARRIER_EXPECT_TX(mb0, 36864 + STAGE_TX);
        bulkcp(sb + QH_OFF, kth + (size_t)(2 * qb) * KT_BYTES, 2 * KT_BYTES, mb0);
        bulkcp(sb + QL_OFF, ktl + (size_t)(2 * qb) * KT_BYTES, 2 * KT_BYTES, mb0);
        bulkcp(sb + KH(0), kth, KT_BYTES, mb0);
        bulkcp(sb + KL(0), ktl, KT_BYTES, mb0);
        bulkcp(sb + VS(0), vth, VT_BYTES, mb0);
        MBARRIER_EXPECT_TX(mb1, STAGE_TX);
        bulkcp(sb + KH(1), kth + (size_t)KT_BYTES, KT_BYTES, mb1);
        bulkcp(sb + KL(1), ktl + (size_t)KT_BYTES, KT_BYTES, mb1);
        bulkcp(sb + VS(1), vth + (size_t)VT_BYTES, VT_BYTES, mb1);
    }

    // per-row fixed shifts (diagonal logits)
    const float C0 = g_C[(size_t)b * HW + q0 + i0 + g];
    const float C1 = g_C[(size_t)b * HW + q0 + i0 + g + 8];

    float l0 = 0.0f, l1 = 0.0f;
    float O[32][4];
    #pragma unroll
    for (int t = 0; t < 32; t++)
        #pragma unroll
        for (int r = 0; r < 4; r++) O[t][r] = 0.0f;

    const uint32_t a_row = (uint32_t)(lane & 15);
    const uint32_t a_col = (uint32_t)((lane & 16) >> 1);
    const uint32_t b_row = (uint32_t)((lane & 7) + ((lane & 16) >> 1));
    const uint32_t b_col = (uint32_t)(lane & 8);

    int ph0 = 0, ph1 = 0;

    for (int kt = 0; kt < NKT; kt++) {
        const int st = kt & 1;
        const uint32_t mb = st ? mb1 : mb0;
        if (st == 0) { MBARRIER_WAIT_PARITY(mb0, ph0); ph0 ^= 1; }
        else         { MBARRIER_WAIT_PARITY(mb1, ph1); ph1 ^= 1; }

        // ---- S = Q K^T (16 x 64), fp16 3-term split ----
        float S[8][4];
        #pragma unroll
        for (int t = 0; t < 8; t++)
            #pragma unroll
            for (int r = 0; r < 4; r++) S[t][r] = 0.0f;

        #pragma unroll
        for (int kk = 0; kk < 4; kk++) {
            uint32_t qoff = (i0 + a_row) * PITCH + (kk * 16 + a_col) * 2;
            uint32_t aH0, aH1, aH2, aH3, aL0, aL1, aL2, aL3;
            ldsm4(aH0, aH1, aH2, aH3, sb + QH_OFF + qoff);
            ldsm4(aL0, aL1, aL2, aL3, sb + QL_OFF + qoff);
            #pragma unroll
            for (int p = 0; p < 4; p++) {
                uint32_t koff = (p * 16 + b_row) * PITCH + (kk * 16 + b_col) * 2;
                uint32_t bH0, bH1, bH2, bH3, bL0, bL1, bL2, bL3;
                ldsm4(bH0, bH1, bH2, bH3, sb + KH(st) + koff);
                ldsm4(bL0, bL1, bL2, bL3, sb + KL(st) + koff);
                mma16816(S[2*p],   aH0, aH1, aH2, aH3, bH0, bH1);
                mma16816(S[2*p],   aH0, aH1, aH2, aH3, bL0, bL1);
                mma16816(S[2*p],   aL0, aL1, aL2, aL3, bH0, bH1);
                mma16816(S[2*p+1], aH0, aH1, aH2, aH3, bH2, bH3);
                mma16816(S[2*p+1], aH0, aH1, aH2, aH3, bL2, bL3);
                mma16816(S[2*p+1], aL0, aL1, aL2, aL3, bH2, bH3);
            }
        }

        // ---- P = exp(S - C), lane-local l accumulation ----
        #pragma unroll
        for (int t = 0; t < 8; t++) {
            S[t][0] = __expf(S[t][0] - C0);
            S[t][1] = __expf(S[t][1] - C0);
            S[t][2] = __expf(S[t][2] - C1);
            S[t][3] = __expf(S[t][3] - C1);
            l0 += S[t][0] + S[t][1];
            l1 += S[t][2] + S[t][3];
        }

        // ---- P repack (fp16) ----
        uint32_t Ph[4][4];
        #pragma unroll
        for (int kk = 0; kk < 4; kk++) {
            Ph[kk][0] = packh2(S[2*kk][0],   S[2*kk][1]);
            Ph[kk][1] = packh2(S[2*kk][2],   S[2*kk][3]);
            Ph[kk][2] = packh2(S[2*kk+1][0], S[2*kk+1][1]);
            Ph[kk][3] = packh2(S[2*kk+1][2], S[2*kk+1][3]);
        }

        // ---- O += P V  (16 x 256) ----
        #pragma unroll
        for (int kk = 0; kk < 4; kk++) {
            #pragma unroll
            for (int p = 0; p < 16; p++) {
                uint32_t voff = (p * 16 + b_row) * PITCH + (kk * 16 + b_col) * 2;
                uint32_t v0, v1, v2, v3;
                ldsm4(v0, v1, v2, v3, sb + VS(st) + voff);
                mma16816(O[2*p],   Ph[kk][0], Ph[kk][1], Ph[kk][2], Ph[kk][3], v0, v1);
                mma16816(O[2*p+1], Ph[kk][0], Ph[kk][1], Ph[kk][2], Ph[kk][3], v2, v3);
            }
        }

        // ---- stage handoff ----
        if (w == 0) {
            asm volatile("bar.sync %0, %1;" :: "r"(2 + st), "r"(256) : "memory");
            if (lane == 0 && kt + 2 < NKT) {
                MBARRIER_EXPECT_TX(mb, STAGE_TX);
                bulkcp(sb + KH(st), kth + (size_t)(kt + 2) * KT_BYTES, KT_BYTES, mb);
                bulkcp(sb + KL(st), ktl + (size_t)(kt + 2) * KT_BYTES, KT_BYTES, mb);
                bulkcp(sb + VS(st), vth + (size_t)(kt + 2) * VT_BYTES, VT_BYTES, mb);
            }
        } else {
            asm volatile("bar.arrive %0, %1;" :: "r"(2 + st), "r"(256) : "memory");
        }
    }

    // ---- epilogue ----
    l0 += __shfl_xor_sync(0xffffffffu, l0, 1);
    l0 += __shfl_xor_sync(0xffffffffu, l0, 2);
    l1 += __shfl_xor_sync(0xffffffffu, l1, 1);
    l1 += __shfl_xor_sync(0xffffffffu, l1, 2);

    __syncthreads();
    {
        float* os = (float*)(smem + OS_OFF);
        const float il0 = 1.0f / l0;
        const float il1 = 1.0f / l1;
        #pragma unroll
        for (int t = 0; t < 32; t++) {
            int c = t * 8 + tig * 2;
            os[(c    ) * OPITCH + i0 + g    ] = O[t][0] * il0;
            os[(c + 1) * OPITCH + i0 + g    ] = O[t][1] * il0;
            os[(c    ) * OPITCH + i0 + g + 8] = O[t][2] * il1;
            os[(c + 1) * OPITCH + i0 + g + 8] = O[t][3] * il1;
        }
        __syncthreads();
        #pragma unroll
        for (int cc = 0; cc < 32; cc++) {
            int c = w * 32 + cc;
            float4 v = *(float4*)&os[c * OPITCH + lane * 4];
            *(float4*)&out[((size_t)(b * CV + c)) * HW + q0 + lane * 4] = v;
        }
    }
    __syncthreads();
    if (tid == 0) { MBARRIER_INVAL(mb0); MBARRIER_INVAL(mb1); }
}

// ---------------------------------------------------------------------------
extern "C" void kernel_launch(void* const* d_in, const int* in_sizes, int n_in,
                              void* d_out, int out_size)
{
    const float* x        = (const float*)d_in[0];
    const float* Wk       = (const float*)d_in[1];
    const float* bk       = (const float*)d_in[2];
    const float* bn_gamma = (const float*)d_in[3];
    const float* bn_beta  = (const float*)d_in[4];
    const float* bn_mean  = (const float*)d_in[5];
    const float* bn_var   = (const float*)d_in[6];
    const float* Wv       = (const float*)d_in[7];
    const float* bv       = (const float*)d_in[8];
    float* out = (float*)d_out;

    cudaFuncSetAttribute(flashm_kernel,
                         cudaFuncAttributeMaxDynamicSharedMemorySize, SMEM_TOTAL);
    cudaFuncSetAttribute(proj_v,
                         cudaFuncAttributeMaxDynamicSharedMemorySize, PROJV_SMEM);
    cudaFuncSetAttribute(proj_k,
                         cudaFuncAttributeMaxDynamicSharedMemorySize, PROJK_SMEM);

    proj_k<<<dim3(HW / 128, NB), 256, PROJK_SMEM>>>(
        x, Wk, bk, bn_gamma, bn_beta, bn_mean, bn_var);
    proj_v<<<dim3(HW / 128, NB), 256, PROJV_SMEM>>>(x, Wv, bv);
    flashm_kernel<<<dim3(HW / BQ, NB), 256, SMEM_TOTAL>>>(out);
}

// round 13
// speedup vs baseline: 1.5439x; 1.5439x over previous
#include <cuda_runtime.h>
#include <cuda_fp16.h>
#include <cstdint>
#include <math.h>

#define HW   4096
#define NB   4
#define CIN  256
#define CK   64
#define CV   256
#define BQ   128
#define BK   64
#define NKT  (HW / BK)

#define PITCHE 72                 // tile row pitch (fp16 elements)
#define KT_BYTES  (64 * 144)      // 9216
#define VT_BYTES  (256 * 144)     // 36864

// ---------------- pre-tiled fp16 scratch ----------------
__device__ __align__(1024) __half g_kth[NB * 64 * 64 * PITCHE];   // K hi  [b][kt][r][d]
__device__ __align__(1024) __half g_ktl[NB * 64 * 64 * PITCHE];   // K lo
__device__ __align__(1024) __half g_vth[NB * 64 * 256 * PITCHE];  // V     [b][kt][c][j]
__device__ float g_C[NB * HW];                                    // diag logits |k_t|^2

// ---------------- helpers ----------------
__device__ __forceinline__ uint32_t smem_u32(const void* p) {
    uint32_t a;
    asm("{ .reg .u64 t; cvta.to.shared.u64 t, %1; cvt.u32.u64 %0, t; }" : "=r"(a) : "l"(p));
    return a;
}
__device__ __forceinline__ void bulkcp(uint32_t dst, const void* src, uint32_t bytes,
                                       uint32_t mbar) {
    asm volatile(
        "cp.async.bulk.shared::cluster.global.mbarrier::complete_tx::bytes [%0], [%1], %2, [%3];"
        :: "r"(dst), "l"(src), "r"(bytes), "r"(mbar) : "memory");
}
#define MBARRIER_INIT(mb, cnt) \
    asm volatile("mbarrier.init.shared.b64 [%0], %1;" :: "r"((uint32_t)(mb)), "r"((uint32_t)(cnt)) : "memory")
#define MBARRIER_EXPECT_TX(mb, tx) \
    asm volatile("mbarrier.arrive.expect_tx.shared.b64 _, [%0], %1;" :: "r"((uint32_t)(mb)), "r"((uint32_t)(tx)) : "memory")
#define MBARRIER_INVAL(mb) \
    asm volatile("mbarrier.inval.shared.b64 [%0];" :: "r"((uint32_t)(mb)) : "memory")
#define FENCE_ASYNC_SHARED() asm volatile("fence.proxy.async.shared::cta;" ::: "memory")
#define MBARRIER_WAIT_PARITY(mb, par) do { \
    uint32_t _mb = (uint32_t)(mb); uint32_t _p = (uint32_t)(par); uint32_t _done; \
    asm volatile("{\n\t.reg .pred p;\n\t" \
        "mbarrier.try_wait.parity.acquire.cta.shared::cta.b64 p, [%1], %2;\n\t" \
        "selp.b32 %0, 1, 0, p;\n\t}" : "=r"(_done) : "r"(_mb), "r"(_p) : "memory"); \
    if (!_done) { \
        asm volatile("{\n\t.reg .pred P1;\n\t" \
            "WL_%=:\n\t" \
            "mbarrier.try_wait.parity.acquire.cta.shared::cta.b64 P1, [%0], %1, 0x989680;\n\t" \
            "@P1 bra.uni WD_%=;\n\t" \
            "bra.uni WL_%=;\n\t" \
            "WD_%=:\n\t}" :: "r"(_mb), "r"(_p) : "memory"); \
    } } while (0)

__device__ __forceinline__ void ldsm4(uint32_t& r0, uint32_t& r1, uint32_t& r2, uint32_t& r3,
                                      uint32_t addr) {
    asm volatile("ldmatrix.sync.aligned.m8n8.x4.shared.b16 {%0,%1,%2,%3}, [%4];"
                 : "=r"(r0), "=r"(r1), "=r"(r2), "=r"(r3) : "r"(addr));
}
__device__ __forceinline__ void ldsm4t(uint32_t& r0, uint32_t& r1, uint32_t& r2, uint32_t& r3,
                                       uint32_t addr) {
    asm volatile("ldmatrix.sync.aligned.m8n8.x4.trans.shared.b16 {%0,%1,%2,%3}, [%4];"
                 : "=r"(r0), "=r"(r1), "=r"(r2), "=r"(r3) : "r"(addr));
}
__device__ __forceinline__ void mma16816(float (&d)[4],
                                         uint32_t a0, uint32_t a1, uint32_t a2, uint32_t a3,
                                         uint32_t b0, uint32_t b1) {
    asm volatile("mma.sync.aligned.m16n8k16.row.col.f32.f16.f16.f32 "
                 "{%0,%1,%2,%3}, {%4,%5,%6,%7}, {%8,%9}, {%0,%1,%2,%3};"
                 : "+f"(d[0]), "+f"(d[1]), "+f"(d[2]), "+f"(d[3])
                 : "r"(a0), "r"(a1), "r"(a2), "r"(a3), "r"(b0), "r"(b1));
}
__device__ __forceinline__ void hsplit(float x, __half& h, __half& l) {
    h = __float2half_rn(x);
    l = __float2half_rn(x - __half2float(h));
}
__device__ __forceinline__ uint32_t pack2h(__half a, __half b) {
    __half2 t(a, b);
    return *reinterpret_cast<uint32_t*>(&t);
}
__device__ __forceinline__ uint32_t packh2(float x, float y) {
    __half2 t = __floats2half2_rn(x, y);
    return *reinterpret_cast<uint32_t*>(&t);
}
__device__ __forceinline__ uint32_t packl2(float x, float y) {
    __half hx = __float2half_rn(x), hy = __float2half_rn(y);
    return pack2h(__float2half_rn(x - __half2float(hx)),
                  __float2half_rn(y - __half2float(hy)));
}

// ================= projection smem layouts (t-tile = 64) =================
// x tile: [c(64)][t(64)] fp16, pitch 144B (trans-ldsm source)
#define PKXH 0
#define PKXL 9216
#define KWH  18432
#define KWL  27648
#define KCP  36864
#define PROJK_SMEM (36864 + 256)            // 37120

#define PVXH 0
#define VWH  9216
#define PROJV_SMEM (9216 + 36864)           // 46080

// ---------------------------------------------------------------------------
// V projection: single-fp16 HMMA. Grid (64 t-tiles, NB). 256 thr.
// CTA: 256 co x 64 t. Warp (wm,wn): co base wm*64 (4 tiles of 16), t base wn*32.
// ---------------------------------------------------------------------------
__global__ __launch_bounds__(256) void proj_v(
    const float* __restrict__ x, const float* __restrict__ Wv,
    const float* __restrict__ bv)
{
    extern __shared__ char ps[];
    const uint32_t sb = smem_u32(ps);
    const int tid = threadIdx.x;
    const int w = tid >> 5, lane = tid & 31;
    const int g = lane >> 2, tig = lane & 3;
    const int wm = w & 3, wn = w >> 2;
    const int kt = blockIdx.x, b = blockIdx.y;
    const int t0 = kt * 64;

    const uint32_t a_row = lane & 15, a_col = (lane & 16) >> 1;
    const uint32_t bt_row = (lane & 7) + (lane & 8), bt_col = (lane & 16) >> 1;

    float d[4][4][4];
    #pragma unroll
    for (int mi = 0; mi < 4; mi++)
        #pragma unroll
        for (int nb = 0; nb < 4; nb++)
            #pragma unroll
            for (int r = 0; r < 4; r++) d[mi][nb][r] = 0.0f;

    for (int c0 = 0; c0 < CIN; c0 += 64) {
        __syncthreads();
        // x chunk [64 c][64 t] -> fp16 (hi only)
        #pragma unroll
        for (int it = 0; it < 4; it++) {
            int v = tid + it * 256;
            int c = v >> 4, t4 = v & 15;
            float4 f = *(const float4*)&x[((size_t)(b * CIN + c0 + c)) * HW + t0 + t4 * 4];
            *(uint2*)(ps + PVXH + c * 144 + t4 * 8) =
                make_uint2(packh2(f.x, f.y), packh2(f.z, f.w));
        }
        // W chunk [256 co][64 c] -> fp16
        #pragma unroll
        for (int it = 0; it < 16; it++) {
            int v = tid + it * 256;
            int row = v >> 4, c4 = v & 15;
            float4 f = *(const float4*)&Wv[(size_t)row * CIN + c0 + c4 * 4];
            *(uint2*)(ps + VWH + row * 144 + c4 * 8) =
                make_uint2(packh2(f.x, f.y), packh2(f.z, f.w));
        }
        __syncthreads();

        #pragma unroll
        for (int ks = 0; ks < 4; ks++) {
            uint32_t a[4][4];
            #pragma unroll
            for (int mi = 0; mi < 4; mi++)
                ldsm4(a[mi][0], a[mi][1], a[mi][2], a[mi][3],
                      sb + VWH + (wm * 64 + mi * 16 + a_row) * 144 + (ks * 16 + a_col) * 2);
            #pragma unroll
            for (int nj = 0; nj < 2; nj++) {
                uint32_t b0, b1, b2, b3;
                ldsm4t(b0, b1, b2, b3,
                       sb + PVXH + (ks * 16 + bt_row) * 144 + (wn * 32 + nj * 16 + bt_col) * 2);
                #pragma unroll
                for (int mi = 0; mi < 4; mi++) {
                    mma16816(d[mi][2 * nj],     a[mi][0], a[mi][1], a[mi][2], a[mi][3], b0, b1);
                    mma16816(d[mi][2 * nj + 1], a[mi][0], a[mi][1], a[mi][2], a[mi][3], b2, b3);
                }
            }
        }
    }

    // store: V tile [b][kt][c][j]
    __half* vt = g_vth + ((size_t)(b * 64 + kt) * 256) * PITCHE;
    #pragma unroll
    for (int mi = 0; mi < 4; mi++) {
        int coA = wm * 64 + mi * 16 + g;
        int coB = coA + 8;
        float bzA = bv[coA], bzB = bv[coB];
        #pragma unroll
        for (int nb = 0; nb < 4; nb++) {
            int j = wn * 32 + nb * 8 + tig * 2;
            *(uint32_t*)&vt[(size_t)coA * PITCHE + j] =
                packh2(d[mi][nb][0] + bzA, d[mi][nb][1] + bzA);
            *(uint32_t*)&vt[(size_t)coB * PITCHE + j] =
                packh2(d[mi][nb][2] + bzB, d[mi][nb][3] + bzB);
        }
    }
}

// ---------------------------------------------------------------------------
// K projection: 3-term fp16-split HMMA + BN fold + diag C. Grid (64, NB).
// CTA: 64 co x 64 t. Warp (wm,wn): co base wm*16, t base wn*32.
// ---------------------------------------------------------------------------
__global__ __launch_bounds__(256) void proj_k(
    const float* __restrict__ x, const float* __restrict__ Wk,
    const float* __restrict__ bk,
    const float* __restrict__ bn_gamma, const float* __restrict__ bn_beta,
    const float* __restrict__ bn_mean,  const float* __restrict__ bn_var)
{
    extern __shared__ char ps[];
    const uint32_t sb = smem_u32(ps);
    const int tid = threadIdx.x;
    const int w = tid >> 5, lane = tid & 31;
    const int g = lane >> 2, tig = lane & 3;
    const int wm = w & 3, wn = w >> 2;
    const int kt = blockIdx.x, b = blockIdx.y;
    const int t0 = kt * 64;

    const uint32_t a_row = lane & 15, a_col = (lane & 16) >> 1;
    const uint32_t bt_row = (lane & 7) + (lane & 8), bt_col = (lane & 16) >> 1;

    float* CPf = (float*)(ps + KCP);
    if (tid < 64) CPf[tid] = 0.0f;

    float d[4][4];
    #pragma unroll
    for (int nb = 0; nb < 4; nb++)
        #pragma unroll
        for (int r = 0; r < 4; r++) d[nb][r] = 0.0f;

    for (int c0 = 0; c0 < CIN; c0 += 64) {
        __syncthreads();
        // x chunk [64 c][64 t] hi/lo
        #pragma unroll
        for (int it = 0; it < 4; it++) {
            int v = tid + it * 256;
            int c = v >> 4, t4 = v & 15;
            float4 f = *(const float4*)&x[((size_t)(b * CIN + c0 + c)) * HW + t0 + t4 * 4];
            *(uint2*)(ps + PKXH + c * 144 + t4 * 8) =
                make_uint2(packh2(f.x, f.y), packh2(f.z, f.w));
            *(uint2*)(ps + PKXL + c * 144 + t4 * 8) =
                make_uint2(packl2(f.x, f.y), packl2(f.z, f.w));
        }
        // W chunk [64 co][64 c] hi/lo
        #pragma unroll
        for (int it = 0; it < 4; it++) {
            int v = tid + it * 256;
            int row = v >> 4, c4 = v & 15;
            float4 f = *(const float4*)&Wk[(size_t)row * CIN + c0 + c4 * 4];
            *(uint2*)(ps + KWH + row * 144 + c4 * 8) =
                make_uint2(packh2(f.x, f.y), packh2(f.z, f.w));
            *(uint2*)(ps + KWL + row * 144 + c4 * 8) =
                make_uint2(packl2(f.x, f.y), packl2(f.z, f.w));
        }
        __syncthreads();

        #pragma unroll
        for (int ks = 0; ks < 4; ks++) {
            uint32_t ah[4], al[4];
            ldsm4(ah[0], ah[1], ah[2], ah[3],
                  sb + KWH + (wm * 16 + a_row) * 144 + (ks * 16 + a_col) * 2);
            ldsm4(al[0], al[1], al[2], al[3],
                  sb + KWL + (wm * 16 + a_row) * 144 + (ks * 16 + a_col) * 2);
            #pragma unroll
            for (int nj = 0; nj < 2; nj++) {
                uint32_t bh0, bh1, bh2, bh3, bl0, bl1, bl2, bl3;
                uint32_t xoff = (ks * 16 + bt_row) * 144 + (wn * 32 + nj * 16 + bt_col) * 2;
                ldsm4t(bh0, bh1, bh2, bh3, sb + PKXH + xoff);
                ldsm4t(bl0, bl1, bl2, bl3, sb + PKXL + xoff);
                mma16816(d[2 * nj],     ah[0], ah[1], ah[2], ah[3], bh0, bh1);
                mma16816(d[2 * nj],     ah[0], ah[1], ah[2], ah[3], bl0, bl1);
                mma16816(d[2 * nj],     al[0], al[1], al[2], al[3], bh0, bh1);
                mma16816(d[2 * nj + 1], ah[0], ah[1], ah[2], ah[3], bh2, bh3);
                mma16816(d[2 * nj + 1], ah[0], ah[1], ah[2], ah[3], bl2, bl3);
                mma16816(d[2 * nj + 1], al[0], al[1], al[2], al[3], bh2, bh3);
            }
        }
    }

    // BN fold, store K tile [b][kt][r][d] hi/lo, accumulate C = |k_t|^2
    const int co0 = wm * 16 + g, co1 = co0 + 8;
    float inv0 = bn_gamma[co0] * rsqrtf(bn_var[co0] + 1e-5f);
    float add0 = bn_beta[co0] - bn_mean[co0] * inv0 + bk[co0] * inv0;
    float inv1 = bn_gamma[co1] * rsqrtf(bn_var[co1] + 1e-5f);
    float add1 = bn_beta[co1] - bn_mean[co1] * inv1 + bk[co1] * inv1;
    __half* kh = g_kth + ((size_t)(b * 64 + kt) * 64) * PITCHE;
    __half* kl = g_ktl + ((size_t)(b * 64 + kt) * 64) * PITCHE;

    #pragma unroll
    for (int nb = 0; nb < 4; nb++) {
        int r = wn * 32 + nb * 8 + tig * 2;
        float k00 = d[nb][0] * inv0 + add0;   // (co0, r)
        float k01 = d[nb][1] * inv0 + add0;   // (co0, r+1)
        float k10 = d[nb][2] * inv1 + add1;   // (co1, r)
        float k11 = d[nb][3] * inv1 + add1;   // (co1, r+1)
        __half h, l;
        hsplit(k00, h, l); kh[(size_t)r * PITCHE + co0] = h;       kl[(size_t)r * PITCHE + co0] = l;
        hsplit(k01, h, l); kh[(size_t)(r + 1) * PITCHE + co0] = h; kl[(size_t)(r + 1) * PITCHE + co0] = l;
        hsplit(k10, h, l); kh[(size_t)r * PITCHE + co1] = h;       kl[(size_t)r * PITCHE + co1] = l;
        hsplit(k11, h, l); kh[(size_t)(r + 1) * PITCHE + co1] = h; kl[(size_t)(r + 1) * PITCHE + co1] = l;

        float s0 = k00 * k00 + k10 * k10;   // token r
        float s1 = k01 * k01 + k11 * k11;   // token r+1
        s0 += __shfl_xor_sync(0xffffffffu, s0, 4);
        s0 += __shfl_xor_sync(0xffffffffu, s0, 8);
        s0 += __shfl_xor_sync(0xffffffffu, s0, 16);
        s1 += __shfl_xor_sync(0xffffffffu, s1, 4);
        s1 += __shfl_xor_sync(0xffffffffu, s1, 8);
        s1 += __shfl_xor_sync(0xffffffffu, s1, 16);
        if (lane < 4) {
            atomicAdd(&CPf[wn * 32 + nb * 8 + lane * 2], s0);
            atomicAdd(&CPf[wn * 32 + nb * 8 + lane * 2 + 1], s1);
        }
    }
    __syncthreads();
    if (tid < 64) g_C[(size_t)b * HW + t0 + tid] = CPf[tid];
}

// ================= flash smem layout =================
#define PITCH  144
#define QH_OFF 0
#define QL_OFF 18432
#define KBASE  36864
#define KH(st) (KBASE + (st) * KT_BYTES)
#define KL(st) (KBASE + 2 * KT_BYTES + (st) * KT_BYTES)
#define VBASE  (KBASE + 4 * KT_BYTES)
#define VS(st) (VBASE + (st) * VT_BYTES)
#define MB_OFF (VBASE + 2 * VT_BYTES)
#define SMEM_TOTAL (MB_OFF + 64)
#define OS_OFF 0
#define OPITCH 132
#define STAGE_TX (2 * KT_BYTES + VT_BYTES)

// ---------------------------------------------------------------------------
// Flash: fixed-shift softmax (P = exp(s - C), no max, no rescale).
// ---------------------------------------------------------------------------
__global__ __launch_bounds__(256, 1) void flashm_kernel(float* __restrict__ out)
{
    extern __shared__ char smem[];
    const uint32_t sb = smem_u32(smem);
    const int tid  = threadIdx.x;
    const int w    = tid >> 5;
    const int lane = tid & 31;
    const int g    = lane >> 2;
    const int tig  = lane & 3;
    const int i0   = w * 16;

    const int qb = blockIdx.x;
    const int q0 = qb * BQ;
    const int b  = blockIdx.y;

    const char* kth = (const char*)g_kth + (size_t)(b * 64) * KT_BYTES;
    const char* ktl = (const char*)g_ktl + (size_t)(b * 64) * KT_BYTES;
    const char* vth = (const char*)g_vth + (size_t)(b * 64) * VT_BYTES;

    const uint32_t mb0 = sb + MB_OFF;
    const uint32_t mb1 = sb + MB_OFF + 8;

    if (tid == 0) {
        MBARRIER_INIT(mb0, 1);
        MBARRIER_INIT(mb1, 1);
        FENCE_ASYNC_SHARED();
    }
    __syncthreads();

    if (tid == 0) {
        MBARRIER_EXPECT_TX(mb0, 36864 + STAGE_TX);
        bulkcp(sb + QH_OFF, kth + (size_t)(2 * qb) * KT_BYTES, 2 * KT_BYTES, mb0);
        bulkcp(sb + QL_OFF, ktl + (size_t)(2 * qb) * KT_BYTES, 2 * KT_BYTES, mb0);
        bulkcp(sb + KH(0), kth, KT_BYTES, mb0);
        bulkcp(sb + KL(0), ktl, KT_BYTES, mb0);
        bulkcp(sb + VS(0), vth, VT_BYTES, mb0);
        MBARRIER_EXPECT_TX(mb1, STAGE_TX);
        bulkcp(sb + KH(1), kth + (size_t)KT_BYTES, KT_BYTES, mb1);
        bulkcp(sb + KL(1), ktl + (size_t)KT_BYTES, KT_BYTES, mb1);
        bulkcp(sb + VS(1), vth + (size_t)VT_BYTES, VT_BYTES, mb1);
    }

    // per-row fixed shifts (diagonal logits)
    const float C0 = g_C[(size_t)b * HW + q0 + i0 + g];
    const float C1 = g_C[(size_t)b * HW + q0 + i0 + g + 8];

    float l0 = 0.0f, l1 = 0.0f;
    float O[32][4];
    #pragma unroll
    for (int t = 0; t < 32; t++)
        #pragma unroll
        for (int r = 0; r < 4; r++) O[t][r] = 0.0f;

    const uint32_t a_row = (uint32_t)(lane & 15);
    const uint32_t a_col = (uint32_t)((lane & 16) >> 1);
    const uint32_t b_row = (uint32_t)((lane & 7) + ((lane & 16) >> 1));
    const uint32_t b_col = (uint32_t)(lane & 8);

    int ph0 = 0, ph1 = 0;

    for (int kt = 0; kt < NKT; kt++) {
        const int st = kt & 1;
        const uint32_t mb = st ? mb1 : mb0;
        if (st == 0) { MBARRIER_WAIT_PARITY(mb0, ph0); ph0 ^= 1; }
        else         { MBARRIER_WAIT_PARITY(mb1, ph1); ph1 ^= 1; }

        // ---- S = Q K^T (16 x 64), fp16 3-term split ----
        float S[8][4];
        #pragma unroll
        for (int t = 0; t < 8; t++)
            #pragma unroll
            for (int r = 0; r < 4; r++) S[t][r] = 0.0f;

        #pragma unroll
        for (int kk = 0; kk < 4; kk++) {
            uint32_t qoff = (i0 + a_row) * PITCH + (kk * 16 + a_col) * 2;
            uint32_t aH0, aH1, aH2, aH3, aL0, aL1, aL2, aL3;
            ldsm4(aH0, aH1, aH2, aH3, sb + QH_OFF + qoff);
            ldsm4(aL0, aL1, aL2, aL3, sb + QL_OFF + qoff);
            #pragma unroll
            for (int p = 0; p < 4; p++) {
                uint32_t koff = (p * 16 + b_row) * PITCH + (kk * 16 + b_col) * 2;
                uint32_t bH0, bH1, bH2, bH3, bL0, bL1, bL2, bL3;
                ldsm4(bH0, bH1, bH2, bH3, sb + KH(st) + koff);
                ldsm4(bL0, bL1, bL2, bL3, sb + KL(st) + koff);
                mma16816(S[2*p],   aH0, aH1, aH2, aH3, bH0, bH1);
                mma16816(S[2*p],   aH0, aH1, aH2, aH3, bL0, bL1);
                mma16816(S[2*p],   aL0, aL1, aL2, aL3, bH0, bH1);
                mma16816(S[2*p+1], aH0, aH1, aH2, aH3, bH2, bH3);
                mma16816(S[2*p+1], aH0, aH1, aH2, aH3, bL2, bL3);
                mma16816(S[2*p+1], aL0, aL1, aL2, aL3, bH2, bH3);
            }
        }

        // ---- P = exp(S - C), lane-local l accumulation ----
        #pragma unroll
        for (int t = 0; t < 8; t++) {
            S[t][0] = __expf(S[t][0] - C0);
            S[t][1] = __expf(S[t][1] - C0);
            S[t][2] = __expf(S[t][2] - C1);
            S[t][3] = __expf(S[t][3] - C1);
            l0 += S[t][0] + S[t][1];
            l1 += S[t][2] + S[t][3];
        }

        // ---- P repack (fp16) ----
        uint32_t Ph[4][4];
        #pragma unroll
        for (int kk = 0; kk < 4; kk++) {
            Ph[kk][0] = packh2(S[2*kk][0],   S[2*kk][1]);
            Ph[kk][1] = packh2(S[2*kk][2],   S[2*kk][3]);
            Ph[kk][2] = packh2(S[2*kk+1][0], S[2*kk+1][1]);
            Ph[kk][3] = packh2(S[2*kk+1][2], S[2*kk+1][3]);
        }

        // ---- O += P V  (16 x 256) ----
        #pragma unroll
        for (int kk = 0; kk < 4; kk++) {
            #pragma unroll
            for (int p = 0; p < 16; p++) {
                uint32_t voff = (p * 16 + b_row) * PITCH + (kk * 16 + b_col) * 2;
                uint32_t v0, v1, v2, v3;
                ldsm4(v0, v1, v2, v3, sb + VS(st) + voff);
                mma16816(O[2*p],   Ph[kk][0], Ph[kk][1], Ph[kk][2], Ph[kk][3], v0, v1);
                mma16816(O[2*p+1], Ph[kk][0], Ph[kk][1], Ph[kk][2], Ph[kk][3], v2, v3);
            }
        }

        // ---- stage handoff ----
        if (w == 0) {
            asm volatile("bar.sync %0, %1;" :: "r"(2 + st), "r"(256) : "memory");
            if (lane == 0 && kt + 2 < NKT) {
                MBARRIER_EXPECT_TX(mb, STAGE_TX);
                bulkcp(sb + KH(st), kth + (size_t)(kt + 2) * KT_BYTES, KT_BYTES, mb);
                bulkcp(sb + KL(st), ktl + (size_t)(kt + 2) * KT_BYTES, KT_BYTES, mb);
                bulkcp(sb + VS(st), vth + (size_t)(kt + 2) * VT_BYTES, VT_BYTES, mb);
            }
        } else {
            asm volatile("bar.arrive %0, %1;" :: "r"(2 + st), "r"(256) : "memory");
        }
    }

    // ---- epilogue ----
    l0 += __shfl_xor_sync(0xffffffffu, l0, 1);
    l0 += __shfl_xor_sync(0xffffffffu, l0, 2);
    l1 += __shfl_xor_sync(0xffffffffu, l1, 1);
    l1 += __shfl_xor_sync(0xffffffffu, l1, 2);

    __syncthreads();
    {
        float* os = (float*)(smem + OS_OFF);
        const float il0 = 1.0f / l0;
        const float il1 = 1.0f / l1;
        #pragma unroll
        for (int t = 0; t < 32; t++) {
            int c = t * 8 + tig * 2;
            os[(c    ) * OPITCH + i0 + g    ] = O[t][0] * il0;
            os[(c + 1) * OPITCH + i0 + g    ] = O[t][1] * il0;
            os[(c    ) * OPITCH + i0 + g + 8] = O[t][2] * il1;
            os[(c + 1) * OPITCH + i0 + g + 8] = O[t][3] * il1;
        }
        __syncthreads();
        #pragma unroll
        for (int cc = 0; cc < 32; cc++) {
            int c = w * 32 + cc;
            float4 v = *(float4*)&os[c * OPITCH + lane * 4];
            *(float4*)&out[((size_t)(b * CV + c)) * HW + q0 + lane * 4] = v;
        }
    }
    __syncthreads();
    if (tid == 0) { MBARRIER_INVAL(mb0); MBARRIER_INVAL(mb1); }
}

// ---------------------------------------------------------------------------
extern "C" void kernel_launch(void* const* d_in, const int* in_sizes, int n_in,
                              void* d_out, int out_size)
{
    const float* x        = (const float*)d_in[0];
    const float* Wk       = (const float*)d_in[1];
    const float* bk       = (const float*)d_in[2];
    const float* bn_gamma = (const float*)d_in[3];
    const float* bn_beta  = (const float*)d_in[4];
    const float* bn_mean  = (const float*)d_in[5];
    const float* bn_var   = (const float*)d_in[6];
    const float* Wv       = (const float*)d_in[7];
    const float* bv       = (const float*)d_in[8];
    float* out = (float*)d_out;

    cudaFuncSetAttribute(flashm_kernel,
                         cudaFuncAttributeMaxDynamicSharedMemorySize, SMEM_TOTAL);
    cudaFuncSetAttribute(proj_v,
                         cudaFuncAttributeMaxDynamicSharedMemorySize, PROJV_SMEM);
    cudaFuncSetAttribute(proj_k,
                         cudaFuncAttributeMaxDynamicSharedMemorySize, PROJK_SMEM);

    proj_k<<<dim3(HW / 64, NB), 256, PROJK_SMEM>>>(
        x, Wk, bk, bn_gamma, bn_beta, bn_mean, bn_var);
    proj_v<<<dim3(HW / 64, NB), 256, PROJV_SMEM>>>(x, Wv, bv);
    flashm_kernel<<<dim3(HW / BQ, NB), 256, SMEM_TOTAL>>>(out);
}

// round 14
// speedup vs baseline: 1.6623x; 1.0767x over previous
#include <cuda_runtime.h>
#include <cuda_fp16.h>
#include <cstdint>
#include <math.h>

#define HW   4096
#define NB   4
#define CIN  256
#define CK   64
#define CV   256
#define BQ   128
#define BK   64
#define NKT  (HW / BK)
#define LOG2E 1.4426950408889634f

#define PITCHE 72                 // tile row pitch (fp16 elements)
#define KT_BYTES  (64 * 144)      // 9216
#define VT_BYTES  (256 * 144)     // 36864

// ---------------- pre-tiled fp16 scratch ----------------
__device__ __align__(1024) __half g_kth[NB * 64 * 64 * PITCHE];   // K hi  [b][kt][r][d]
__device__ __align__(1024) __half g_ktl[NB * 64 * 64 * PITCHE];   // K lo
__device__ __align__(1024) __half g_vth[NB * 64 * 256 * PITCHE];  // V     [b][kt][c][j]
__device__ float g_C[NB * HW];                                    // diag logits |k_t|^2

// ---------------- helpers ----------------
__device__ __forceinline__ uint32_t smem_u32(const void* p) {
    uint32_t a;
    asm("{ .reg .u64 t; cvta.to.shared.u64 t, %1; cvt.u32.u64 %0, t; }" : "=r"(a) : "l"(p));
    return a;
}
__device__ __forceinline__ void bulkcp(uint32_t dst, const void* src, uint32_t bytes,
                                       uint32_t mbar) {
    asm volatile(
        "cp.async.bulk.shared::cluster.global.mbarrier::complete_tx::bytes [%0], [%1], %2, [%3];"
        :: "r"(dst), "l"(src), "r"(bytes), "r"(mbar) : "memory");
}
#define MBARRIER_INIT(mb, cnt) \
    asm volatile("mbarrier.init.shared.b64 [%0], %1;" :: "r"((uint32_t)(mb)), "r"((uint32_t)(cnt)) : "memory")
#define MBARRIER_EXPECT_TX(mb, tx) \
    asm volatile("mbarrier.arrive.expect_tx.shared.b64 _, [%0], %1;" :: "r"((uint32_t)(mb)), "r"((uint32_t)(tx)) : "memory")
#define MBARRIER_INVAL(mb) \
    asm volatile("mbarrier.inval.shared.b64 [%0];" :: "r"((uint32_t)(mb)) : "memory")
#define FENCE_ASYNC_SHARED() asm volatile("fence.proxy.async.shared::cta;" ::: "memory")
#define MBARRIER_WAIT_PARITY(mb, par) do { \
    uint32_t _mb = (uint32_t)(mb); uint32_t _p = (uint32_t)(par); uint32_t _done; \
    asm volatile("{\n\t.reg .pred p;\n\t" \
        "mbarrier.try_wait.parity.acquire.cta.shared::cta.b64 p, [%1], %2;\n\t" \
        "selp.b32 %0, 1, 0, p;\n\t}" : "=r"(_done) : "r"(_mb), "r"(_p) : "memory"); \
    if (!_done) { \
        asm volatile("{\n\t.reg .pred P1;\n\t" \
            "WL_%=:\n\t" \
            "mbarrier.try_wait.parity.acquire.cta.shared::cta.b64 P1, [%0], %1, 0x989680;\n\t" \
            "@P1 bra.uni WD_%=;\n\t" \
            "bra.uni WL_%=;\n\t" \
            "WD_%=:\n\t}" :: "r"(_mb), "r"(_p) : "memory"); \
    } } while (0)

__device__ __forceinline__ void ldsm4(uint32_t& r0, uint32_t& r1, uint32_t& r2, uint32_t& r3,
                                      uint32_t addr) {
    asm volatile("ldmatrix.sync.aligned.m8n8.x4.shared.b16 {%0,%1,%2,%3}, [%4];"
                 : "=r"(r0), "=r"(r1), "=r"(r2), "=r"(r3) : "r"(addr));
}
__device__ __forceinline__ void ldsm4t(uint32_t& r0, uint32_t& r1, uint32_t& r2, uint32_t& r3,
                                       uint32_t addr) {
    asm volatile("ldmatrix.sync.aligned.m8n8.x4.trans.shared.b16 {%0,%1,%2,%3}, [%4];"
                 : "=r"(r0), "=r"(r1), "=r"(r2), "=r"(r3) : "r"(addr));
}
__device__ __forceinline__ void mma16816(float (&d)[4],
                                         uint32_t a0, uint32_t a1, uint32_t a2, uint32_t a3,
                                         uint32_t b0, uint32_t b1) {
    asm volatile("mma.sync.aligned.m16n8k16.row.col.f32.f16.f16.f32 "
                 "{%0,%1,%2,%3}, {%4,%5,%6,%7}, {%8,%9}, {%0,%1,%2,%3};"
                 : "+f"(d[0]), "+f"(d[1]), "+f"(d[2]), "+f"(d[3])
                 : "r"(a0), "r"(a1), "r"(a2), "r"(a3), "r"(b0), "r"(b1));
}
__device__ __forceinline__ void hsplit(float x, __half& h, __half& l) {
    h = __float2half_rn(x);
    l = __float2half_rn(x - __half2float(h));
}
__device__ __forceinline__ uint32_t pack2h(__half a, __half b) {
    __half2 t(a, b);
    return *reinterpret_cast<uint32_t*>(&t);
}
__device__ __forceinline__ uint32_t packh2(float x, float y) {
    __half2 t = __floats2half2_rn(x, y);
    return *reinterpret_cast<uint32_t*>(&t);
}
__device__ __forceinline__ uint32_t packl2(float x, float y) {
    __half hx = __float2half_rn(x), hy = __float2half_rn(y);
    return pack2h(__float2half_rn(x - __half2float(hx)),
                  __float2half_rn(y - __half2float(hy)));
}
__device__ __forceinline__ uint32_t ex2h2(uint32_t x) {
    asm("ex2.approx.f16x2 %0, %0;" : "+r"(x));
    return x;
}
__device__ __forceinline__ __half2 u2h2(uint32_t x) {
    return *reinterpret_cast<__half2*>(&x);
}

// ================= fused projection =================
// CTA = one 64-token tile. Computes V (256 co, single fp16) and K (64 co,
// 3-term split) sharing the x tile. Grid (64, NB), 256 thr.
#define FXH  0
#define FXL  9216
#define FWVH 18432
#define FWKH 55296
#define FWKL 64512
#define FCP  73728
#define PROJF_SMEM (73728 + 256)

__global__ __launch_bounds__(256) void projf(
    const float* __restrict__ x,
    const float* __restrict__ Wk, const float* __restrict__ bk,
    const float* __restrict__ bn_gamma, const float* __restrict__ bn_beta,
    const float* __restrict__ bn_mean,  const float* __restrict__ bn_var,
    const float* __restrict__ Wv, const float* __restrict__ bv)
{
    extern __shared__ char ps[];
    const uint32_t sb = smem_u32(ps);
    const int tid = threadIdx.x;
    const int w = tid >> 5, lane = tid & 31;
    const int g = lane >> 2, tig = lane & 3;
    const int wm = w & 3, wn = w >> 2;
    const int kt = blockIdx.x, b = blockIdx.y;
    const int t0 = kt * 64;

    const uint32_t a_row = lane & 15, a_col = (lane & 16) >> 1;
    const uint32_t bt_row = (lane & 7) + (lane & 8), bt_col = (lane & 16) >> 1;

    float* CPf = (float*)(ps + FCP);
    if (tid < 64) CPf[tid] = 0.0f;

    float dv[4][4][4];
    float dk[4][4];
    #pragma unroll
    for (int mi = 0; mi < 4; mi++)
        #pragma unroll
        for (int nb = 0; nb < 4; nb++)
            #pragma unroll
            for (int r = 0; r < 4; r++) dv[mi][nb][r] = 0.0f;
    #pragma unroll
    for (int nb = 0; nb < 4; nb++)
        #pragma unroll
        for (int r = 0; r < 4; r++) dk[nb][r] = 0.0f;

    for (int c0 = 0; c0 < CIN; c0 += 64) {
        __syncthreads();
        // x chunk [64 c][64 t] hi/lo
        #pragma unroll
        for (int it = 0; it < 4; it++) {
            int v = tid + it * 256;
            int c = v >> 4, t4 = v & 15;
            float4 f = *(const float4*)&x[((size_t)(b * CIN + c0 + c)) * HW + t0 + t4 * 4];
            *(uint2*)(ps + FXH + c * 144 + t4 * 8) =
                make_uint2(packh2(f.x, f.y), packh2(f.z, f.w));
            *(uint2*)(ps + FXL + c * 144 + t4 * 8) =
                make_uint2(packl2(f.x, f.y), packl2(f.z, f.w));
        }
        // Wv chunk [256 co][64 c]
        #pragma unroll
        for (int it = 0; it < 16; it++) {
            int v = tid + it * 256;
            int row = v >> 4, c4 = v & 15;
            float4 f = *(const float4*)&Wv[(size_t)row * CIN + c0 + c4 * 4];
            *(uint2*)(ps + FWVH + row * 144 + c4 * 8) =
                make_uint2(packh2(f.x, f.y), packh2(f.z, f.w));
        }
        // Wk chunk [64 co][64 c] hi/lo
        #pragma unroll
        for (int it = 0; it < 4; it++) {
            int v = tid + it * 256;
            int row = v >> 4, c4 = v & 15;
            float4 f = *(const float4*)&Wk[(size_t)row * CIN + c0 + c4 * 4];
            *(uint2*)(ps + FWKH + row * 144 + c4 * 8) =
                make_uint2(packh2(f.x, f.y), packh2(f.z, f.w));
            *(uint2*)(ps + FWKL + row * 144 + c4 * 8) =
                make_uint2(packl2(f.x, f.y), packl2(f.z, f.w));
        }
        __syncthreads();

        #pragma unroll
        for (int ks = 0; ks < 4; ks++) {
            // shared x B-fragments (hi for V and K-hh/lh; lo for K cross terms)
            uint32_t bh[2][4], bl[2][4];
            #pragma unroll
            for (int nj = 0; nj < 2; nj++) {
                uint32_t xoff = (ks * 16 + bt_row) * 144 + (wn * 32 + nj * 16 + bt_col) * 2;
                ldsm4t(bh[nj][0], bh[nj][1], bh[nj][2], bh[nj][3], sb + FXH + xoff);
                ldsm4t(bl[nj][0], bl[nj][1], bl[nj][2], bl[nj][3], sb + FXL + xoff);
            }
            // V: 4 co-tiles of 16
            #pragma unroll
            for (int mi = 0; mi < 4; mi++) {
                uint32_t a0, a1, a2, a3;
                ldsm4(a0, a1, a2, a3,
                      sb + FWVH + (wm * 64 + mi * 16 + a_row) * 144 + (ks * 16 + a_col) * 2);
                #pragma unroll
                for (int nj = 0; nj < 2; nj++) {
                    mma16816(dv[mi][2 * nj],     a0, a1, a2, a3, bh[nj][0], bh[nj][1]);
                    mma16816(dv[mi][2 * nj + 1], a0, a1, a2, a3, bh[nj][2], bh[nj][3]);
                }
            }
            // K: 1 co-tile, 3-term split
            {
                uint32_t ah0, ah1, ah2, ah3, al0, al1, al2, al3;
                ldsm4(ah0, ah1, ah2, ah3,
                      sb + FWKH + (wm * 16 + a_row) * 144 + (ks * 16 + a_col) * 2);
                ldsm4(al0, al1, al2, al3,
                      sb + FWKL + (wm * 16 + a_row) * 144 + (ks * 16 + a_col) * 2);
                #pragma unroll
                for (int nj = 0; nj < 2; nj++) {
                    mma16816(dk[2 * nj],     ah0, ah1, ah2, ah3, bh[nj][0], bh[nj][1]);
                    mma16816(dk[2 * nj],     ah0, ah1, ah2, ah3, bl[nj][0], bl[nj][1]);
                    mma16816(dk[2 * nj],     al0, al1, al2, al3, bh[nj][0], bh[nj][1]);
                    mma16816(dk[2 * nj + 1], ah0, ah1, ah2, ah3, bh[nj][2], bh[nj][3]);
                    mma16816(dk[2 * nj + 1], ah0, ah1, ah2, ah3, bl[nj][2], bl[nj][3]);
                    mma16816(dk[2 * nj + 1], al0, al1, al2, al3, bh[nj][2], bh[nj][3]);
                }
            }
        }
    }

    // ---- V epilogue ----
    __half* vt = g_vth + ((size_t)(b * 64 + kt) * 256) * PITCHE;
    #pragma unroll
    for (int mi = 0; mi < 4; mi++) {
        int coA = wm * 64 + mi * 16 + g;
        int coB = coA + 8;
        float bzA = bv[coA], bzB = bv[coB];
        #pragma unroll
        for (int nb = 0; nb < 4; nb++) {
            int j = wn * 32 + nb * 8 + tig * 2;
            *(uint32_t*)&vt[(size_t)coA * PITCHE + j] =
                packh2(dv[mi][nb][0] + bzA, dv[mi][nb][1] + bzA);
            *(uint32_t*)&vt[(size_t)coB * PITCHE + j] =
                packh2(dv[mi][nb][2] + bzB, dv[mi][nb][3] + bzB);
        }
    }

    // ---- K epilogue: BN fold + tiles + diag C ----
    const int co0 = wm * 16 + g, co1 = co0 + 8;
    float inv0 = bn_gamma[co0] * rsqrtf(bn_var[co0] + 1e-5f);
    float add0 = bn_beta[co0] - bn_mean[co0] * inv0 + bk[co0] * inv0;
    float inv1 = bn_gamma[co1] * rsqrtf(bn_var[co1] + 1e-5f);
    float add1 = bn_beta[co1] - bn_mean[co1] * inv1 + bk[co1] * inv1;
    __half* kh = g_kth + ((size_t)(b * 64 + kt) * 64) * PITCHE;
    __half* kl = g_ktl + ((size_t)(b * 64 + kt) * 64) * PITCHE;

    #pragma unroll
    for (int nb = 0; nb < 4; nb++) {
        int r = wn * 32 + nb * 8 + tig * 2;
        float k00 = dk[nb][0] * inv0 + add0;
        float k01 = dk[nb][1] * inv0 + add0;
        float k10 = dk[nb][2] * inv1 + add1;
        float k11 = dk[nb][3] * inv1 + add1;
        __half h, l;
        hsplit(k00, h, l); kh[(size_t)r * PITCHE + co0] = h;       kl[(size_t)r * PITCHE + co0] = l;
        hsplit(k01, h, l); kh[(size_t)(r + 1) * PITCHE + co0] = h; kl[(size_t)(r + 1) * PITCHE + co0] = l;
        hsplit(k10, h, l); kh[(size_t)r * PITCHE + co1] = h;       kl[(size_t)r * PITCHE + co1] = l;
        hsplit(k11, h, l); kh[(size_t)(r + 1) * PITCHE + co1] = h; kl[(size_t)(r + 1) * PITCHE + co1] = l;

        float s0 = k00 * k00 + k10 * k10;
        float s1 = k01 * k01 + k11 * k11;
        s0 += __shfl_xor_sync(0xffffffffu, s0, 4);
        s0 += __shfl_xor_sync(0xffffffffu, s0, 8);
        s0 += __shfl_xor_sync(0xffffffffu, s0, 16);
        s1 += __shfl_xor_sync(0xffffffffu, s1, 4);
        s1 += __shfl_xor_sync(0xffffffffu, s1, 8);
        s1 += __shfl_xor_sync(0xffffffffu, s1, 16);
        if (lane < 4) {
            atomicAdd(&CPf[wn * 32 + nb * 8 + lane * 2], s0);
            atomicAdd(&CPf[wn * 32 + nb * 8 + lane * 2 + 1], s1);
        }
    }
    __syncthreads();
    if (tid < 64) g_C[(size_t)b * HW + t0 + tid] = CPf[tid];
}

// ================= flash smem layout =================
#define PITCH  144
#define QH_OFF 0
#define QL_OFF 18432
#define KBASE  36864
#define KH(st) (KBASE + (st) * KT_BYTES)
#define KL(st) (KBASE + 2 * KT_BYTES + (st) * KT_BYTES)
#define VBASE  (KBASE + 4 * KT_BYTES)
#define VS(st) (VBASE + (st) * VT_BYTES)
#define MB_OFF (VBASE + 2 * VT_BYTES)
#define SMEM_TOTAL (MB_OFF + 64)
#define OS_OFF 0
#define OPITCH 132
#define STAGE_TX (2 * KT_BYTES + VT_BYTES)

// ---------------------------------------------------------------------------
// Flash: fixed-shift softmax with fp16x2 ex2.
// ---------------------------------------------------------------------------
__global__ __launch_bounds__(256, 1) void flashm_kernel(float* __restrict__ out)
{
    extern __shared__ char smem[];
    const uint32_t sb = smem_u32(smem);
    const int tid  = threadIdx.x;
    const int w    = tid >> 5;
    const int lane = tid & 31;
    const int g    = lane >> 2;
    const int tig  = lane & 3;
    const int i0   = w * 16;

    const int qb = blockIdx.x;
    const int q0 = qb * BQ;
    const int b  = blockIdx.y;

    const char* kth = (const char*)g_kth + (size_t)(b * 64) * KT_BYTES;
    const char* ktl = (const char*)g_ktl + (size_t)(b * 64) * KT_BYTES;
    const char* vth = (const char*)g_vth + (size_t)(b * 64) * VT_BYTES;

    const uint32_t mb0 = sb + MB_OFF;
    const uint32_t mb1 = sb + MB_OFF + 8;

    if (tid == 0) {
        MBARRIER_INIT(mb0, 1);
        MBARRIER_INIT(mb1, 1);
        FENCE_ASYNC_SHARED();
    }
    __syncthreads();

    if (tid == 0) {
        MBARRIER_EXPECT_TX(mb0, 36864 + STAGE_TX);
        bulkcp(sb + QH_OFF, kth + (size_t)(2 * qb) * KT_BYTES, 2 * KT_BYTES, mb0);
        bulkcp(sb + QL_OFF, ktl + (size_t)(2 * qb) * KT_BYTES, 2 * KT_BYTES, mb0);
        bulkcp(sb + KH(0), kth, KT_BYTES, mb0);
        bulkcp(sb + KL(0), ktl, KT_BYTES, mb0);
        bulkcp(sb + VS(0), vth, VT_BYTES, mb0);
        MBARRIER_EXPECT_TX(mb1, STAGE_TX);
        bulkcp(sb + KH(1), kth + (size_t)KT_BYTES, KT_BYTES, mb1);
        bulkcp(sb + KL(1), ktl + (size_t)KT_BYTES, KT_BYTES, mb1);
        bulkcp(sb + VS(1), vth + (size_t)VT_BYTES, VT_BYTES, mb1);
    }

    // per-row fixed shifts (diagonal logits), pre-scaled by log2(e)
    const float mC0 = -g_C[(size_t)b * HW + q0 + i0 + g] * LOG2E;
    const float mC1 = -g_C[(size_t)b * HW + q0 + i0 + g + 8] * LOG2E;

    float l0 = 0.0f, l1 = 0.0f;
    float O[32][4];
    #pragma unroll
    for (int t = 0; t < 32; t++)
        #pragma unroll
        for (int r = 0; r < 4; r++) O[t][r] = 0.0f;

    const uint32_t a_row = (uint32_t)(lane & 15);
    const uint32_t a_col = (uint32_t)((lane & 16) >> 1);
    const uint32_t b_row = (uint32_t)((lane & 7) + ((lane & 16) >> 1));
    const uint32_t b_col = (uint32_t)(lane & 8);

    int ph0 = 0, ph1 = 0;

    for (int kt = 0; kt < NKT; kt++) {
        const int st = kt & 1;
        const uint32_t mb = st ? mb1 : mb0;
        if (st == 0) { MBARRIER_WAIT_PARITY(mb0, ph0); ph0 ^= 1; }
        else         { MBARRIER_WAIT_PARITY(mb1, ph1); ph1 ^= 1; }

        // ---- S = Q K^T (16 x 64), fp16 3-term split ----
        float S[8][4];
        #pragma unroll
        for (int t = 0; t < 8; t++)
            #pragma unroll
            for (int r = 0; r < 4; r++) S[t][r] = 0.0f;

        #pragma unroll
        for (int kk = 0; kk < 4; kk++) {
            uint32_t qoff = (i0 + a_row) * PITCH + (kk * 16 + a_col) * 2;
            uint32_t aH0, aH1, aH2, aH3, aL0, aL1, aL2, aL3;
            ldsm4(aH0, aH1, aH2, aH3, sb + QH_OFF + qoff);
            ldsm4(aL0, aL1, aL2, aL3, sb + QL_OFF + qoff);
            #pragma unroll
            for (int p = 0; p < 4; p++) {
                uint32_t koff = (p * 16 + b_row) * PITCH + (kk * 16 + b_col) * 2;
                uint32_t bH0, bH1, bH2, bH3, bL0, bL1, bL2, bL3;
                ldsm4(bH0, bH1, bH2, bH3, sb + KH(st) + koff);
                ldsm4(bL0, bL1, bL2, bL3, sb + KL(st) + koff);
                mma16816(S[2*p],   aH0, aH1, aH2, aH3, bH0, bH1);
                mma16816(S[2*p],   aH0, aH1, aH2, aH3, bL0, bL1);
                mma16816(S[2*p],   aL0, aL1, aL2, aL3, bH0, bH1);
                mma16816(S[2*p+1], aH0, aH1, aH2, aH3, bH2, bH3);
                mma16816(S[2*p+1], aH0, aH1, aH2, aH3, bL2, bL3);
                mma16816(S[2*p+1], aL0, aL1, aL2, aL3, bH2, bH3);
            }
        }

        // ---- P = ex2(S*log2e - C*log2e) in fp16x2 ----
        uint32_t Ph[4][4];
        #pragma unroll
        for (int kk = 0; kk < 4; kk++) {
            float t00 = fmaf(S[2*kk][0],   LOG2E, mC0);
            float t01 = fmaf(S[2*kk][1],   LOG2E, mC0);
            float t02 = fmaf(S[2*kk][2],   LOG2E, mC1);
            float t03 = fmaf(S[2*kk][3],   LOG2E, mC1);
            float t10 = fmaf(S[2*kk+1][0], LOG2E, mC0);
            float t11 = fmaf(S[2*kk+1][1], LOG2E, mC0);
            float t12 = fmaf(S[2*kk+1][2], LOG2E, mC1);
            float t13 = fmaf(S[2*kk+1][3], LOG2E, mC1);
            Ph[kk][0] = ex2h2(packh2(t00, t01));
            Ph[kk][1] = ex2h2(packh2(t02, t03));
            Ph[kk][2] = ex2h2(packh2(t10, t11));
            Ph[kk][3] = ex2h2(packh2(t12, t13));
        }

        // ---- l accumulation (half2 per-iter, widened to f32) ----
        {
            __half2 acc0 = u2h2(Ph[0][0]), acc1 = u2h2(Ph[0][1]);
            acc0 = __hadd2(acc0, u2h2(Ph[0][2]));
            acc1 = __hadd2(acc1, u2h2(Ph[0][3]));
            #pragma unroll
            for (int kk = 1; kk < 4; kk++) {
                acc0 = __hadd2(acc0, __hadd2(u2h2(Ph[kk][0]), u2h2(Ph[kk][2])));
                acc1 = __hadd2(acc1, __hadd2(u2h2(Ph[kk][1]), u2h2(Ph[kk][3])));
            }
            float2 f0 = __half22float2(acc0);
            float2 f1 = __half22float2(acc1);
            l0 += f0.x + f0.y;
            l1 += f1.x + f1.y;
        }

        // ---- O += P V  (16 x 256) ----
        #pragma unroll
        for (int kk = 0; kk < 4; kk++) {
            #pragma unroll
            for (int p = 0; p < 16; p++) {
                uint32_t voff = (p * 16 + b_row) * PITCH + (kk * 16 + b_col) * 2;
                uint32_t v0, v1, v2, v3;
                ldsm4(v0, v1, v2, v3, sb + VS(st) + voff);
                mma16816(O[2*p],   Ph[kk][0], Ph[kk][1], Ph[kk][2], Ph[kk][3], v0, v1);
                mma16816(O[2*p+1], Ph[kk][0], Ph[kk][1], Ph[kk][2], Ph[kk][3], v2, v3);
            }
        }

        // ---- stage handoff ----
        if (w == 0) {
            asm volatile("bar.sync %0, %1;" :: "r"(2 + st), "r"(256) : "memory");
            if (lane == 0 && kt + 2 < NKT) {
                MBARRIER_EXPECT_TX(mb, STAGE_TX);
                bulkcp(sb + KH(st), kth + (size_t)(kt + 2) * KT_BYTES, KT_BYTES, mb);
                bulkcp(sb + KL(st), ktl + (size_t)(kt + 2) * KT_BYTES, KT_BYTES, mb);
                bulkcp(sb + VS(st), vth + (size_t)(kt + 2) * VT_BYTES, VT_BYTES, mb);
            }
        } else {
            asm volatile("bar.arrive %0, %1;" :: "r"(2 + st), "r"(256) : "memory");
        }
    }

    // ---- epilogue ----
    l0 += __shfl_xor_sync(0xffffffffu, l0, 1);
    l0 += __shfl_xor_sync(0xffffffffu, l0, 2);
    l1 += __shfl_xor_sync(0xffffffffu, l1, 1);
    l1 += __shfl_xor_sync(0xffffffffu, l1, 2);

    __syncthreads();
    {
        float* os = (float*)(smem + OS_OFF);
        const float il0 = 1.0f / l0;
        const float il1 = 1.0f / l1;
        #pragma unroll
        for (int t = 0; t < 32; t++) {
            int c = t * 8 + tig * 2;
            os[(c    ) * OPITCH + i0 + g    ] = O[t][0] * il0;
            os[(c + 1) * OPITCH + i0 + g    ] = O[t][1] * il0;
            os[(c    ) * OPITCH + i0 + g + 8] = O[t][2] * il1;
            os[(c + 1) * OPITCH + i0 + g + 8] = O[t][3] * il1;
        }
        __syncthreads();
        #pragma unroll
        for (int cc = 0; cc < 32; cc++) {
            int c = w * 32 + cc;
            float4 v = *(float4*)&os[c * OPITCH + lane * 4];
            *(float4*)&out[((size_t)(b * CV + c)) * HW + q0 + lane * 4] = v;
        }
    }
    __syncthreads();
    if (tid == 0) { MBARRIER_INVAL(mb0); MBARRIER_INVAL(mb1); }
}

// ---------------------------------------------------------------------------
extern "C" void kernel_launch(void* const* d_in, const int* in_sizes, int n_in,
                              void* d_out, int out_size)
{
    const float* x        = (const float*)d_in[0];
    const float* Wk       = (const float*)d_in[1];
    const float* bk       = (const float*)d_in[2];
    const float* bn_gamma = (const float*)d_in[3];
    const float* bn_beta  = (const float*)d_in[4];
    const float* bn_mean  = (const float*)d_in[5];
    const float* bn_var   = (const float*)d_in[6];
    const float* Wv       = (const float*)d_in[7];
    const float* bv       = (const float*)d_in[8];
    float* out = (float*)d_out;

    cudaFuncSetAttribute(flashm_kernel,
                         cudaFuncAttributeMaxDynamicSharedMemorySize, SMEM_TOTAL);
    cudaFuncSetAttribute(projf,
                         cudaFuncAttributeMaxDynamicSharedMemorySize, PROJF_SMEM);

    projf<<<dim3(HW / 64, NB), 256, PROJF_SMEM>>>(
        x, Wk, bk, bn_gamma, bn_beta, bn_mean, bn_var, Wv, bv);
    flashm_kernel<<<dim3(HW / BQ, NB), 256, SMEM_TOTAL>>>(out);
}

// round 15
// speedup vs baseline: 1.7522x; 1.0541x over previous
#include <cuda_runtime.h>
#include <cuda_fp16.h>
#include <cstdint>
#include <math.h>

#define HW   4096
#define NB   4
#define CIN  256
#define CK   64
#define CV   256
#define BQ   128
#define BK   64
#define NKT  (HW / BK)
#define LOG2E 1.4426950408889634f
#define SKIP_THR (-30.0f)          // log2 threshold: P < 2^-30 ~ 1e-9 -> tile negligible

#define PITCHE 72                 // tile row pitch (fp16 elements)
#define KT_BYTES  (64 * 144)      // 9216
#define VT_BYTES  (256 * 144)     // 36864

// ---------------- pre-tiled fp16 scratch ----------------
__device__ __align__(1024) __half g_kth[NB * 64 * 64 * PITCHE];   // K hi  [b][kt][r][d]
__device__ __align__(1024) __half g_ktl[NB * 64 * 64 * PITCHE];   // K lo
__device__ __align__(1024) __half g_vth[NB * 64 * 256 * PITCHE];  // V     [b][kt][c][j]
__device__ float g_C[NB * HW];                                    // diag logits |k_t|^2

// ---------------- helpers ----------------
__device__ __forceinline__ uint32_t smem_u32(const void* p) {
    uint32_t a;
    asm("{ .reg .u64 t; cvta.to.shared.u64 t, %1; cvt.u32.u64 %0, t; }" : "=r"(a) : "l"(p));
    return a;
}
__device__ __forceinline__ void bulkcp(uint32_t dst, const void* src, uint32_t bytes,
                                       uint32_t mbar) {
    asm volatile(
        "cp.async.bulk.shared::cluster.global.mbarrier::complete_tx::bytes [%0], [%1], %2, [%3];"
        :: "r"(dst), "l"(src), "r"(bytes), "r"(mbar) : "memory");
}
#define MBARRIER_INIT(mb, cnt) \
    asm volatile("mbarrier.init.shared.b64 [%0], %1;" :: "r"((uint32_t)(mb)), "r"((uint32_t)(cnt)) : "memory")
#define MBARRIER_EXPECT_TX(mb, tx) \
    asm volatile("mbarrier.arrive.expect_tx.shared.b64 _, [%0], %1;" :: "r"((uint32_t)(mb)), "r"((uint32_t)(tx)) : "memory")
#define MBARRIER_INVAL(mb) \
    asm volatile("mbarrier.inval.shared.b64 [%0];" :: "r"((uint32_t)(mb)) : "memory")
#define FENCE_ASYNC_SHARED() asm volatile("fence.proxy.async.shared::cta;" ::: "memory")
#define MBARRIER_WAIT_PARITY(mb, par) do { \
    uint32_t _mb = (uint32_t)(mb); uint32_t _p = (uint32_t)(par); uint32_t _done; \
    asm volatile("{\n\t.reg .pred p;\n\t" \
        "mbarrier.try_wait.parity.acquire.cta.shared::cta.b64 p, [%1], %2;\n\t" \
        "selp.b32 %0, 1, 0, p;\n\t}" : "=r"(_done) : "r"(_mb), "r"(_p) : "memory"); \
    if (!_done) { \
        asm volatile("{\n\t.reg .pred P1;\n\t" \
            "WL_%=:\n\t" \
            "mbarrier.try_wait.parity.acquire.cta.shared::cta.b64 P1, [%0], %1, 0x989680;\n\t" \
            "@P1 bra.uni WD_%=;\n\t" \
            "bra.uni WL_%=;\n\t" \
            "WD_%=:\n\t}" :: "r"(_mb), "r"(_p) : "memory"); \
    } } while (0)

__device__ __forceinline__ void ldsm4(uint32_t& r0, uint32_t& r1, uint32_t& r2, uint32_t& r3,
                                      uint32_t addr) {
    asm volatile("ldmatrix.sync.aligned.m8n8.x4.shared.b16 {%0,%1,%2,%3}, [%4];"
                 : "=r"(r0), "=r"(r1), "=r"(r2), "=r"(r3) : "r"(addr));
}
__device__ __forceinline__ void ldsm4t(uint32_t& r0, uint32_t& r1, uint32_t& r2, uint32_t& r3,
                                       uint32_t addr) {
    asm volatile("ldmatrix.sync.aligned.m8n8.x4.trans.shared.b16 {%0,%1,%2,%3}, [%4];"
                 : "=r"(r0), "=r"(r1), "=r"(r2), "=r"(r3) : "r"(addr));
}
__device__ __forceinline__ void mma16816(float (&d)[4],
                                         uint32_t a0, uint32_t a1, uint32_t a2, uint32_t a3,
                                         uint32_t b0, uint32_t b1) {
    asm volatile("mma.sync.aligned.m16n8k16.row.col.f32.f16.f16.f32 "
                 "{%0,%1,%2,%3}, {%4,%5,%6,%7}, {%8,%9}, {%0,%1,%2,%3};"
                 : "+f"(d[0]), "+f"(d[1]), "+f"(d[2]), "+f"(d[3])
                 : "r"(a0), "r"(a1), "r"(a2), "r"(a3), "r"(b0), "r"(b1));
}
__device__ __forceinline__ void hsplit(float x, __half& h, __half& l) {
    h = __float2half_rn(x);
    l = __float2half_rn(x - __half2float(h));
}
__device__ __forceinline__ uint32_t pack2h(__half a, __half b) {
    __half2 t(a, b);
    return *reinterpret_cast<uint32_t*>(&t);
}
__device__ __forceinline__ uint32_t packh2(float x, float y) {
    __half2 t = __floats2half2_rn(x, y);
    return *reinterpret_cast<uint32_t*>(&t);
}
__device__ __forceinline__ uint32_t packl2(float x, float y) {
    __half hx = __float2half_rn(x), hy = __float2half_rn(y);
    return pack2h(__float2half_rn(x - __half2float(hx)),
                  __float2half_rn(y - __half2float(hy)));
}
__device__ __forceinline__ uint32_t ex2h2(uint32_t x) {
    asm("ex2.approx.f16x2 %0, %0;" : "+r"(x));
    return x;
}
__device__ __forceinline__ __half2 u2h2(uint32_t x) {
    return *reinterpret_cast<__half2*>(&x);
}

// ================= fused projection =================
// CTA = one 64-token tile. Computes V (256 co, single fp16) and K (64 co,
// 3-term split) sharing the x tile. Grid (64, NB), 256 thr.
#define FXH  0
#define FXL  9216
#define FWVH 18432
#define FWKH 55296
#define FWKL 64512
#define FCP  73728
#define PROJF_SMEM (73728 + 256)

__global__ __launch_bounds__(256) void projf(
    const float* __restrict__ x,
    const float* __restrict__ Wk, const float* __restrict__ bk,
    const float* __restrict__ bn_gamma, const float* __restrict__ bn_beta,
    const float* __restrict__ bn_mean,  const float* __restrict__ bn_var,
    const float* __restrict__ Wv, const float* __restrict__ bv)
{
    extern __shared__ char ps[];
    const uint32_t sb = smem_u32(ps);
    const int tid = threadIdx.x;
    const int w = tid >> 5, lane = tid & 31;
    const int g = lane >> 2, tig = lane & 3;
    const int wm = w & 3, wn = w >> 2;
    const int kt = blockIdx.x, b = blockIdx.y;
    const int t0 = kt * 64;

    const uint32_t a_row = lane & 15, a_col = (lane & 16) >> 1;
    const uint32_t bt_row = (lane & 7) + (lane & 8), bt_col = (lane & 16) >> 1;

    float* CPf = (float*)(ps + FCP);
    if (tid < 64) CPf[tid] = 0.0f;

    float dv[4][4][4];
    float dk[4][4];
    #pragma unroll
    for (int mi = 0; mi < 4; mi++)
        #pragma unroll
        for (int nb = 0; nb < 4; nb++)
            #pragma unroll
            for (int r = 0; r < 4; r++) dv[mi][nb][r] = 0.0f;
    #pragma unroll
    for (int nb = 0; nb < 4; nb++)
        #pragma unroll
        for (int r = 0; r < 4; r++) dk[nb][r] = 0.0f;

    for (int c0 = 0; c0 < CIN; c0 += 64) {
        __syncthreads();
        // x chunk [64 c][64 t] hi/lo
        #pragma unroll
        for (int it = 0; it < 4; it++) {
            int v = tid + it * 256;
            int c = v >> 4, t4 = v & 15;
            float4 f = *(const float4*)&x[((size_t)(b * CIN + c0 + c)) * HW + t0 + t4 * 4];
            *(uint2*)(ps + FXH + c * 144 + t4 * 8) =
                make_uint2(packh2(f.x, f.y), packh2(f.z, f.w));
            *(uint2*)(ps + FXL + c * 144 + t4 * 8) =
                make_uint2(packl2(f.x, f.y), packl2(f.z, f.w));
        }
        // Wv chunk [256 co][64 c]
        #pragma unroll
        for (int it = 0; it < 16; it++) {
            int v = tid + it * 256;
            int row = v >> 4, c4 = v & 15;
            float4 f = *(const float4*)&Wv[(size_t)row * CIN + c0 + c4 * 4];
            *(uint2*)(ps + FWVH + row * 144 + c4 * 8) =
                make_uint2(packh2(f.x, f.y), packh2(f.z, f.w));
        }
        // Wk chunk [64 co][64 c] hi/lo
        #pragma unroll
        for (int it = 0; it < 4; it++) {
            int v = tid + it * 256;
            int row = v >> 4, c4 = v & 15;
            float4 f = *(const float4*)&Wk[(size_t)row * CIN + c0 + c4 * 4];
            *(uint2*)(ps + FWKH + row * 144 + c4 * 8) =
                make_uint2(packh2(f.x, f.y), packh2(f.z, f.w));
            *(uint2*)(ps + FWKL + row * 144 + c4 * 8) =
                make_uint2(packl2(f.x, f.y), packl2(f.z, f.w));
        }
        __syncthreads();

        #pragma unroll
        for (int ks = 0; ks < 4; ks++) {
            // shared x B-fragments (hi for V and K-hh/lh; lo for K cross terms)
            uint32_t bh[2][4], bl[2][4];
            #pragma unroll
            for (int nj = 0; nj < 2; nj++) {
                uint32_t xoff = (ks * 16 + bt_row) * 144 + (wn * 32 + nj * 16 + bt_col) * 2;
                ldsm4t(bh[nj][0], bh[nj][1], bh[nj][2], bh[nj][3], sb + FXH + xoff);
                ldsm4t(bl[nj][0], bl[nj][1], bl[nj][2], bl[nj][3], sb + FXL + xoff);
            }
            // V: 4 co-tiles of 16
            #pragma unroll
            for (int mi = 0; mi < 4; mi++) {
                uint32_t a0, a1, a2, a3;
                ldsm4(a0, a1, a2, a3,
                      sb + FWVH + (wm * 64 + mi * 16 + a_row) * 144 + (ks * 16 + a_col) * 2);
                #pragma unroll
                for (int nj = 0; nj < 2; nj++) {
                    mma16816(dv[mi][2 * nj],     a0, a1, a2, a3, bh[nj][0], bh[nj][1]);
                    mma16816(dv[mi][2 * nj + 1], a0, a1, a2, a3, bh[nj][2], bh[nj][3]);
                }
            }
            // K: 1 co-tile, 3-term split
            {
                uint32_t ah0, ah1, ah2, ah3, al0, al1, al2, al3;
                ldsm4(ah0, ah1, ah2, ah3,
                      sb + FWKH + (wm * 16 + a_row) * 144 + (ks * 16 + a_col) * 2);
                ldsm4(al0, al1, al2, al3,
                      sb + FWKL + (wm * 16 + a_row) * 144 + (ks * 16 + a_col) * 2);
                #pragma unroll
                for (int nj = 0; nj < 2; nj++) {
                    mma16816(dk[2 * nj],     ah0, ah1, ah2, ah3, bh[nj][0], bh[nj][1]);
                    mma16816(dk[2 * nj],     ah0, ah1, ah2, ah3, bl[nj][0], bl[nj][1]);
                    mma16816(dk[2 * nj],     al0, al1, al2, al3, bh[nj][0], bh[nj][1]);
                    mma16816(dk[2 * nj + 1], ah0, ah1, ah2, ah3, bh[nj][2], bh[nj][3]);
                    mma16816(dk[2 * nj + 1], ah0, ah1, ah2, ah3, bl[nj][2], bl[nj][3]);
                    mma16816(dk[2 * nj + 1], al0, al1, al2, al3, bh[nj][2], bh[nj][3]);
                }
            }
        }
    }

    // ---- V epilogue ----
    __half* vt = g_vth + ((size_t)(b * 64 + kt) * 256) * PITCHE;
    #pragma unroll
    for (int mi = 0; mi < 4; mi++) {
        int coA = wm * 64 + mi * 16 + g;
        int coB = coA + 8;
        float bzA = bv[coA], bzB = bv[coB];
        #pragma unroll
        for (int nb = 0; nb < 4; nb++) {
            int j = wn * 32 + nb * 8 + tig * 2;
            *(uint32_t*)&vt[(size_t)coA * PITCHE + j] =
                packh2(dv[mi][nb][0] + bzA, dv[mi][nb][1] + bzA);
            *(uint32_t*)&vt[(size_t)coB * PITCHE + j] =
                packh2(dv[mi][nb][2] + bzB, dv[mi][nb][3] + bzB);
        }
    }

    // ---- K epilogue: BN fold + tiles + diag C ----
    const int co0 = wm * 16 + g, co1 = co0 + 8;
    float inv0 = bn_gamma[co0] * rsqrtf(bn_var[co0] + 1e-5f);
    float add0 = bn_beta[co0] - bn_mean[co0] * inv0 + bk[co0] * inv0;
    float inv1 = bn_gamma[co1] * rsqrtf(bn_var[co1] + 1e-5f);
    float add1 = bn_beta[co1] - bn_mean[co1] * inv1 + bk[co1] * inv1;
    __half* kh = g_kth + ((size_t)(b * 64 + kt) * 64) * PITCHE;
    __half* kl = g_ktl + ((size_t)(b * 64 + kt) * 64) * PITCHE;

    #pragma unroll
    for (int nb = 0; nb < 4; nb++) {
        int r = wn * 32 + nb * 8 + tig * 2;
        float k00 = dk[nb][0] * inv0 + add0;
        float k01 = dk[nb][1] * inv0 + add0;
        float k10 = dk[nb][2] * inv1 + add1;
        float k11 = dk[nb][3] * inv1 + add1;
        __half h, l;
        hsplit(k00, h, l); kh[(size_t)r * PITCHE + co0] = h;       kl[(size_t)r * PITCHE + co0] = l;
        hsplit(k01, h, l); kh[(size_t)(r + 1) * PITCHE + co0] = h; kl[(size_t)(r + 1) * PITCHE + co0] = l;
        hsplit(k10, h, l); kh[(size_t)r * PITCHE + co1] = h;       kl[(size_t)r * PITCHE + co1] = l;
        hsplit(k11, h, l); kh[(size_t)(r + 1) * PITCHE + co1] = h; kl[(size_t)(r + 1) * PITCHE + co1] = l;

        float s0 = k00 * k00 + k10 * k10;
        float s1 = k01 * k01 + k11 * k11;
        s0 += __shfl_xor_sync(0xffffffffu, s0, 4);
        s0 += __shfl_xor_sync(0xffffffffu, s0, 8);
        s0 += __shfl_xor_sync(0xffffffffu, s0, 16);
        s1 += __shfl_xor_sync(0xffffffffu, s1, 4);
        s1 += __shfl_xor_sync(0xffffffffu, s1, 8);
        s1 += __shfl_xor_sync(0xffffffffu, s1, 16);
        if (lane < 4) {
            atomicAdd(&CPf[wn * 32 + nb * 8 + lane * 2], s0);
            atomicAdd(&CPf[wn * 32 + nb * 8 + lane * 2 + 1], s1);
        }
    }
    __syncthreads();
    if (tid < 64) g_C[(size_t)b * HW + t0 + tid] = CPf[tid];
}

// ================= flash smem layout =================
#define PITCH  144
#define QH_OFF 0
#define QL_OFF 18432
#define KBASE  36864
#define KH(st) (KBASE + (st) * KT_BYTES)
#define KL(st) (KBASE + 2 * KT_BYTES + (st) * KT_BYTES)
#define VBASE  (KBASE + 4 * KT_BYTES)
#define VS(st) (VBASE + (st) * VT_BYTES)
#define MB_OFF (VBASE + 2 * VT_BYTES)
#define SMEM_TOTAL (MB_OFF + 64)
#define OS_OFF 0
#define OPITCH 132
#define STAGE_TX (2 * KT_BYTES + VT_BYTES)

// ---------------------------------------------------------------------------
// Flash: fixed-shift softmax + data-adaptive tile skipping.
// A key tile whose max shifted exponent < SKIP_THR (P < 1e-9 everywhere)
// contributes nothing detectable: skip exp/pack/l/PV for it.
// ---------------------------------------------------------------------------
__global__ __launch_bounds__(256, 1) void flashm_kernel(float* __restrict__ out)
{
    extern __shared__ char smem[];
    const uint32_t sb = smem_u32(smem);
    const int tid  = threadIdx.x;
    const int w    = tid >> 5;
    const int lane = tid & 31;
    const int g    = lane >> 2;
    const int tig  = lane & 3;
    const int i0   = w * 16;

    const int qb = blockIdx.x;
    const int q0 = qb * BQ;
    const int b  = blockIdx.y;

    const char* kth = (const char*)g_kth + (size_t)(b * 64) * KT_BYTES;
    const char* ktl = (const char*)g_ktl + (size_t)(b * 64) * KT_BYTES;
    const char* vth = (const char*)g_vth + (size_t)(b * 64) * VT_BYTES;

    const uint32_t mb0 = sb + MB_OFF;
    const uint32_t mb1 = sb + MB_OFF + 8;

    if (tid == 0) {
        MBARRIER_INIT(mb0, 1);
        MBARRIER_INIT(mb1, 1);
        FENCE_ASYNC_SHARED();
    }
    __syncthreads();

    if (tid == 0) {
        MBARRIER_EXPECT_TX(mb0, 36864 + STAGE_TX);
        bulkcp(sb + QH_OFF, kth + (size_t)(2 * qb) * KT_BYTES, 2 * KT_BYTES, mb0);
        bulkcp(sb + QL_OFF, ktl + (size_t)(2 * qb) * KT_BYTES, 2 * KT_BYTES, mb0);
        bulkcp(sb + KH(0), kth, KT_BYTES, mb0);
        bulkcp(sb + KL(0), ktl, KT_BYTES, mb0);
        bulkcp(sb + VS(0), vth, VT_BYTES, mb0);
        MBARRIER_EXPECT_TX(mb1, STAGE_TX);
        bulkcp(sb + KH(1), kth + (size_t)KT_BYTES, KT_BYTES, mb1);
        bulkcp(sb + KL(1), ktl + (size_t)KT_BYTES, KT_BYTES, mb1);
        bulkcp(sb + VS(1), vth + (size_t)VT_BYTES, VT_BYTES, mb1);
    }

    // per-row fixed shifts (diagonal logits), pre-scaled by log2(e)
    const float mC0 = -g_C[(size_t)b * HW + q0 + i0 + g] * LOG2E;
    const float mC1 = -g_C[(size_t)b * HW + q0 + i0 + g + 8] * LOG2E;

    float l0 = 0.0f, l1 = 0.0f;
    float O[32][4];
    #pragma unroll
    for (int t = 0; t < 32; t++)
        #pragma unroll
        for (int r = 0; r < 4; r++) O[t][r] = 0.0f;

    const uint32_t a_row = (uint32_t)(lane & 15);
    const uint32_t a_col = (uint32_t)((lane & 16) >> 1);
    const uint32_t b_row = (uint32_t)((lane & 7) + ((lane & 16) >> 1));
    const uint32_t b_col = (uint32_t)(lane & 8);

    int ph0 = 0, ph1 = 0;

    for (int kt = 0; kt < NKT; kt++) {
        const int st = kt & 1;
        const uint32_t mb = st ? mb1 : mb0;
        if (st == 0) { MBARRIER_WAIT_PARITY(mb0, ph0); ph0 ^= 1; }
        else         { MBARRIER_WAIT_PARITY(mb1, ph1); ph1 ^= 1; }

        // ---- S = Q K^T (16 x 64), fp16 3-term split ----
        float S[8][4];
        #pragma unroll
        for (int t = 0; t < 8; t++)
            #pragma unroll
            for (int r = 0; r < 4; r++) S[t][r] = 0.0f;

        #pragma unroll
        for (int kk = 0; kk < 4; kk++) {
            uint32_t qoff = (i0 + a_row) * PITCH + (kk * 16 + a_col) * 2;
            uint32_t aH0, aH1, aH2, aH3, aL0, aL1, aL2, aL3;
            ldsm4(aH0, aH1, aH2, aH3, sb + QH_OFF + qoff);
            ldsm4(aL0, aL1, aL2, aL3, sb + QL_OFF + qoff);
            #pragma unroll
            for (int p = 0; p < 4; p++) {
                uint32_t koff = (p * 16 + b_row) * PITCH + (kk * 16 + b_col) * 2;
                uint32_t bH0, bH1, bH2, bH3, bL0, bL1, bL2, bL3;
                ldsm4(bH0, bH1, bH2, bH3, sb + KH(st) + koff);
                ldsm4(bL0, bL1, bL2, bL3, sb + KL(st) + koff);
                mma16816(S[2*p],   aH0, aH1, aH2, aH3, bH0, bH1);
                mma16816(S[2*p],   aH0, aH1, aH2, aH3, bL0, bL1);
                mma16816(S[2*p],   aL0, aL1, aL2, aL3, bH0, bH1);
                mma16816(S[2*p+1], aH0, aH1, aH2, aH3, bH2, bH3);
                mma16816(S[2*p+1], aH0, aH1, aH2, aH3, bL2, bL3);
                mma16816(S[2*p+1], aL0, aL1, aL2, aL3, bH2, bH3);
            }
        }

        // ---- shifted log2 exponents t = S*log2e - C*log2e; warp max ----
        float tmax = -1e30f;
        #pragma unroll
        for (int t = 0; t < 8; t++) {
            S[t][0] = fmaf(S[t][0], LOG2E, mC0);
            S[t][1] = fmaf(S[t][1], LOG2E, mC0);
            S[t][2] = fmaf(S[t][2], LOG2E, mC1);
            S[t][3] = fmaf(S[t][3], LOG2E, mC1);
            tmax = fmaxf(tmax, fmaxf(fmaxf(S[t][0], S[t][1]), fmaxf(S[t][2], S[t][3])));
        }
        #pragma unroll
        for (int off = 16; off >= 1; off >>= 1)
            tmax = fmaxf(tmax, __shfl_xor_sync(0xffffffffu, tmax, off));

        if (tmax > SKIP_THR) {
            // ---- P = ex2(t) in fp16x2 ----
            uint32_t Ph[4][4];
            #pragma unroll
            for (int kk = 0; kk < 4; kk++) {
                Ph[kk][0] = ex2h2(packh2(S[2*kk][0],   S[2*kk][1]));
                Ph[kk][1] = ex2h2(packh2(S[2*kk][2],   S[2*kk][3]));
                Ph[kk][2] = ex2h2(packh2(S[2*kk+1][0], S[2*kk+1][1]));
                Ph[kk][3] = ex2h2(packh2(S[2*kk+1][2], S[2*kk+1][3]));
            }

            // ---- l accumulation (half2 per-iter, widened to f32) ----
            {
                __half2 acc0 = u2h2(Ph[0][0]), acc1 = u2h2(Ph[0][1]);
                acc0 = __hadd2(acc0, u2h2(Ph[0][2]));
                acc1 = __hadd2(acc1, u2h2(Ph[0][3]));
                #pragma unroll
                for (int kk = 1; kk < 4; kk++) {
                    acc0 = __hadd2(acc0, __hadd2(u2h2(Ph[kk][0]), u2h2(Ph[kk][2])));
                    acc1 = __hadd2(acc1, __hadd2(u2h2(Ph[kk][1]), u2h2(Ph[kk][3])));
                }
                float2 f0 = __half22float2(acc0);
                float2 f1 = __half22float2(acc1);
                l0 += f0.x + f0.y;
                l1 += f1.x + f1.y;
            }

            // ---- O += P V  (16 x 256) ----
            #pragma unroll
            for (int kk = 0; kk < 4; kk++) {
                #pragma unroll
                for (int p = 0; p < 16; p++) {
                    uint32_t voff = (p * 16 + b_row) * PITCH + (kk * 16 + b_col) * 2;
                    uint32_t v0, v1, v2, v3;
                    ldsm4(v0, v1, v2, v3, sb + VS(st) + voff);
                    mma16816(O[2*p],   Ph[kk][0], Ph[kk][1], Ph[kk][2], Ph[kk][3], v0, v1);
                    mma16816(O[2*p+1], Ph[kk][0], Ph[kk][1], Ph[kk][2], Ph[kk][3], v2, v3);
                }
            }
        }

        // ---- stage handoff ----
        if (w == 0) {
            asm volatile("bar.sync %0, %1;" :: "r"(2 + st), "r"(256) : "memory");
            if (lane == 0 && kt + 2 < NKT) {
                MBARRIER_EXPECT_TX(mb, STAGE_TX);
                bulkcp(sb + KH(st), kth + (size_t)(kt + 2) * KT_BYTES, KT_BYTES, mb);
                bulkcp(sb + KL(st), ktl + (size_t)(kt + 2) * KT_BYTES, KT_BYTES, mb);
                bulkcp(sb + VS(st), vth + (size_t)(kt + 2) * VT_BYTES, VT_BYTES, mb);
            }
        } else {
            asm volatile("bar.arrive %0, %1;" :: "r"(2 + st), "r"(256) : "memory");
        }
    }

    // ---- epilogue ----
    l0 += __shfl_xor_sync(0xffffffffu, l0, 1);
    l0 += __shfl_xor_sync(0xffffffffu, l0, 2);
    l1 += __shfl_xor_sync(0xffffffffu, l1, 1);
    l1 += __shfl_xor_sync(0xffffffffu, l1, 2);

    __syncthreads();
    {
        float* os = (float*)(smem + OS_OFF);
        const float il0 = 1.0f / l0;
        const float il1 = 1.0f / l1;
        #pragma unroll
        for (int t = 0; t < 32; t++) {
            int c = t * 8 + tig * 2;
            os[(c    ) * OPITCH + i0 + g    ] = O[t][0] * il0;
            os[(c + 1) * OPITCH + i0 + g    ] = O[t][1] * il0;
            os[(c    ) * OPITCH + i0 + g + 8] = O[t][2] * il1;
            os[(c + 1) * OPITCH + i0 + g + 8] = O[t][3] * il1;
        }
        __syncthreads();
        #pragma unroll
        for (int cc = 0; cc < 32; cc++) {
            int c = w * 32 + cc;
            float4 v = *(float4*)&os[c * OPITCH + lane * 4];
            *(float4*)&out[((size_t)(b * CV + c)) * HW + q0 + lane * 4] = v;
        }
    }
    __syncthreads();
    if (tid == 0) { MBARRIER_INVAL(mb0); MBARRIER_INVAL(mb1); }
}

// ---------------------------------------------------------------------------
extern "C" void kernel_launch(void* const* d_in, const int* in_sizes, int n_in,
                              void* d_out, int out_size)
{
    const float* x        = (const float*)d_in[0];
    const float* Wk       = (const float*)d_in[1];
    const float* bk       = (const float*)d_in[2];
    const float* bn_gamma = (const float*)d_in[3];
    const float* bn_beta  = (const float*)d_in[4];
    const float* bn_mean  = (const float*)d_in[5];
    const float* bn_var   = (const float*)d_in[6];
    const float* Wv       = (const float*)d_in[7];
    const float* bv       = (const float*)d_in[8];
    float* out = (float*)d_out;

    cudaFuncSetAttribute(flashm_kernel,
                         cudaFuncAttributeMaxDynamicSharedMemorySize, SMEM_TOTAL);
    cudaFuncSetAttribute(projf,
                         cudaFuncAttributeMaxDynamicSharedMemorySize, PROJF_SMEM);

    projf<<<dim3(HW / 64, NB), 256, PROJF_SMEM>>>(
        x, Wk, bk, bn_gamma, bn_beta, bn_mean, bn_var, Wv, bv);
    flashm_kernel<<<dim3(HW / BQ, NB), 256, SMEM_TOTAL>>>(out);
}